// round 4
// baseline (speedup 1.0000x reference)
#include <cuda_runtime.h>

// ---------------------------------------------------------------------------
// GCN: 3x (GraphConv norm='both') with BN+ReLU between, log_softmax at end.
// N=100000 nodes, E=1.6M edges, D=128, C=40.
//
// Pipeline per launch (all on default stream, graph-capturable, alloc-free):
//   deg count (int atomics) -> deg^-1/2
//   L1: zero agg; prop (gather x*dout, v4-red scatter); GEMM128 (+din,+b1)
//       bn stats + finalize (a,b folded)
//   L2: zero agg; prop with fused BN+ReLU on gather; GEMM128 (+din,+b2)
//       bn stats + finalize
//   L3: zero agg; prop with fused BN+ReLU; GEMM 128->40 + log_softmax fused
// ---------------------------------------------------------------------------

#define NMAX 100096
#define DD 128

__device__ float g_bufA[(size_t)NMAX * DD];   // agg buffer
__device__ float g_bufB[(size_t)NMAX * DD];   // gemm output / next layer input
__device__ float g_dout_is[NMAX];
__device__ float g_din_is[NMAX];
__device__ int   g_deg_out[NMAX];
__device__ int   g_deg_in[NMAX];
__device__ float g_colsum[DD];  // zero-initialized; bn_finalize re-zeros after use
__device__ float g_colsq[DD];
__device__ float g_bn_a[DD];
__device__ float g_bn_b[DD];

// ---------------------------------------------------------------------------
__global__ void zero_f4_kernel(float4* __restrict__ p, int n4) {
    int i = blockIdx.x * blockDim.x + threadIdx.x;
    int stride = gridDim.x * blockDim.x;
    float4 z = make_float4(0.f, 0.f, 0.f, 0.f);
    for (; i < n4; i += stride) p[i] = z;
}

__global__ void zero_deg_kernel(int n) {
    int i = blockIdx.x * blockDim.x + threadIdx.x;
    if (i < n) { g_deg_out[i] = 0; g_deg_in[i] = 0; }
}

__global__ void deg_count_kernel(const int* __restrict__ src,
                                 const int* __restrict__ dst, int E) {
    int i = blockIdx.x * blockDim.x + threadIdx.x;
    if (i < E) {
        atomicAdd(&g_deg_out[src[i]], 1);
        atomicAdd(&g_deg_in[dst[i]], 1);
    }
}

__global__ void deg_inv_kernel(int n) {
    int i = blockIdx.x * blockDim.x + threadIdx.x;
    if (i < n) {
        g_dout_is[i] = rsqrtf(fmaxf((float)g_deg_out[i], 1.f));
        g_din_is[i]  = rsqrtf(fmaxf((float)g_deg_in[i], 1.f));
    }
}

// ---------------------------------------------------------------------------
// Edge propagation: one warp per edge. Lane l handles features [4l, 4l+4).
// msg = (USE_BN ? relu(in*a + b) : in) * dout_is[src]; agg[dst] += msg.
// Scatter via red.global.add.v4.f32 (sm_90+), 1 vector red per lane.
// ---------------------------------------------------------------------------
template <int USE_BN>
__global__ void __launch_bounds__(256) prop_kernel(
    const float4* __restrict__ in, const int* __restrict__ src,
    const int* __restrict__ dst, float* __restrict__ agg, int E)
{
    int w = blockIdx.x * 8 + (threadIdx.x >> 5);
    if (w >= E) return;
    int lane = threadIdx.x & 31;
    int s0 = 0, d0 = 0;
    if (lane == 0) { s0 = __ldg(src + w); d0 = __ldg(dst + w); }
    int s = __shfl_sync(0xffffffffu, s0, 0);
    int d = __shfl_sync(0xffffffffu, d0, 0);

    float4 v = __ldg(in + (size_t)s * 32 + lane);
    if (USE_BN) {
        float4 a = __ldg(((const float4*)g_bn_a) + lane);
        float4 b = __ldg(((const float4*)g_bn_b) + lane);
        v.x = fmaxf(fmaf(v.x, a.x, b.x), 0.f);
        v.y = fmaxf(fmaf(v.y, a.y, b.y), 0.f);
        v.z = fmaxf(fmaf(v.z, a.z, b.z), 0.f);
        v.w = fmaxf(fmaf(v.w, a.w, b.w), 0.f);
    }
    float sc = __ldg(&g_dout_is[s]);
    v.x *= sc; v.y *= sc; v.z *= sc; v.w *= sc;

    float* addr = agg + (size_t)d * 128 + lane * 4;
    asm volatile("red.global.add.v4.f32 [%0], {%1, %2, %3, %4};"
                 :: "l"(addr), "f"(v.x), "f"(v.y), "f"(v.z), "f"(v.w)
                 : "memory");
}

// ---------------------------------------------------------------------------
// GEMM: out[r, c] = din_is[r] * (A[r,:] @ W[:,c]) + bias[c],  D=128 square.
// Block: 64 rows x 128 cols. 256 threads, each computes 8 rows x 4 cols.
// W (64KB) + A^T (padded, 34KB) in shared.
// ---------------------------------------------------------------------------
#define SMEM128 ((128 * 128 + 128 * 68) * 4)

__global__ void __launch_bounds__(256) gemm128_kernel(
    const float* __restrict__ A, const float* __restrict__ W,
    const float* __restrict__ bias, float* __restrict__ out, int N)
{
    extern __shared__ float sm[];
    float* sW  = sm;              // [k][c], 128*128
    float* sAT = sm + 128 * 128;  // [k][r], leading dim 68 (pad: banks + align)
    int tid  = threadIdx.x;
    int row0 = blockIdx.x * 64;

    {
        const float4* W4 = (const float4*)W;
        float4* sW4 = (float4*)sW;
        #pragma unroll
        for (int i = 0; i < 16; i++) sW4[tid + i * 256] = __ldg(W4 + tid + i * 256);
    }
    #pragma unroll
    for (int ii = 0; ii < 8; ii++) {
        int i  = tid + ii * 256;           // 2048 float4 total
        int r  = i >> 5;
        int k4 = (i & 31) << 2;
        int rr = row0 + r;
        float4 v = make_float4(0.f, 0.f, 0.f, 0.f);
        if (rr < N) v = __ldg((const float4*)(A + (size_t)rr * 128 + k4));
        sAT[(k4 + 0) * 68 + r] = v.x;
        sAT[(k4 + 1) * 68 + r] = v.y;
        sAT[(k4 + 2) * 68 + r] = v.z;
        sAT[(k4 + 3) * 68 + r] = v.w;
    }
    __syncthreads();

    int cg = (tid & 31) << 2;   // cols [cg, cg+4)
    int rg = (tid >> 5) << 3;   // rows [rg, rg+8) (warp-uniform -> LDS broadcast)
    float acc[8][4];
    #pragma unroll
    for (int i = 0; i < 8; i++)
        #pragma unroll
        for (int j = 0; j < 4; j++) acc[i][j] = 0.f;

    #pragma unroll 8
    for (int k = 0; k < 128; k++) {
        float4 wv = *(const float4*)(sW + k * 128 + cg);
        float4 a0 = *(const float4*)(sAT + k * 68 + rg);
        float4 a1 = *(const float4*)(sAT + k * 68 + rg + 4);
        float ar[8] = {a0.x, a0.y, a0.z, a0.w, a1.x, a1.y, a1.z, a1.w};
        #pragma unroll
        for (int i = 0; i < 8; i++) {
            acc[i][0] = fmaf(ar[i], wv.x, acc[i][0]);
            acc[i][1] = fmaf(ar[i], wv.y, acc[i][1]);
            acc[i][2] = fmaf(ar[i], wv.z, acc[i][2]);
            acc[i][3] = fmaf(ar[i], wv.w, acc[i][3]);
        }
    }

    float4 bv = __ldg((const float4*)(bias + cg));
    #pragma unroll
    for (int i = 0; i < 8; i++) {
        int rr = row0 + rg + i;
        if (rr < N) {
            float sc = __ldg(&g_din_is[rr]);
            float4 o;
            o.x = fmaf(acc[i][0], sc, bv.x);
            o.y = fmaf(acc[i][1], sc, bv.y);
            o.z = fmaf(acc[i][2], sc, bv.z);
            o.w = fmaf(acc[i][3], sc, bv.w);
            *(float4*)(out + (size_t)rr * 128 + cg) = o;
        }
    }
}

// ---------------------------------------------------------------------------
// BN stats: per-feature sum / sum-of-squares over all N rows.
// ---------------------------------------------------------------------------
__global__ void bn_stats_kernel(const float* __restrict__ h, int N) {
    int c = threadIdx.x;  // 128 threads
    float s = 0.f, q = 0.f;
    for (int r = blockIdx.x; r < N; r += gridDim.x) {
        float v = h[(size_t)r * 128 + c];
        s += v;
        q = fmaf(v, v, q);
    }
    atomicAdd(&g_colsum[c], s);
    atomicAdd(&g_colsq[c], q);
}

__global__ void bn_finalize_kernel(const float* __restrict__ g,
                                   const float* __restrict__ be, float invN) {
    int c = threadIdx.x;  // 128 threads
    float mu  = g_colsum[c] * invN;
    float var = fmaf(-mu, mu, g_colsq[c] * invN);
    float a   = __ldg(g + c) * rsqrtf(var + 1e-5f);
    g_bn_a[c] = a;
    g_bn_b[c] = fmaf(-mu, a, __ldg(be + c));
    g_colsum[c] = 0.f;  // reset for next BN / next launch
    g_colsq[c]  = 0.f;
}

// ---------------------------------------------------------------------------
// Final layer: out = log_softmax(din_is[r] * (A[r,:] @ W3) + b3), C=40.
// Block: 64 rows. W3 zero-padded to 128x64 in shared. 4x4 per thread.
// Softmax done per-row from a shared staging tile.
// ---------------------------------------------------------------------------
#define SMEM40 ((128 * 64 + 128 * 68 + 64 * 40) * 4)

__global__ void __launch_bounds__(256) gemm40_kernel(
    const float* __restrict__ A, const float* __restrict__ W3,
    const float* __restrict__ b3, float* __restrict__ out, int N)
{
    extern __shared__ float sm[];
    float* sW   = sm;                       // [k][c] padded to 64 cols
    float* sAT  = sm + 128 * 64;            // [k][r] ld 68
    float* sOut = sAT + 128 * 68;           // [64][40]
    int tid  = threadIdx.x;
    int row0 = blockIdx.x * 64;

    for (int i = tid; i < 128 * 64; i += 256) sW[i] = 0.f;
    __syncthreads();
    for (int i = tid; i < 128 * 40; i += 256) {
        int k = i / 40, c = i - k * 40;
        sW[k * 64 + c] = __ldg(W3 + i);
    }
    #pragma unroll
    for (int ii = 0; ii < 8; ii++) {
        int i  = tid + ii * 256;
        int r  = i >> 5;
        int k4 = (i & 31) << 2;
        int rr = row0 + r;
        float4 v = make_float4(0.f, 0.f, 0.f, 0.f);
        if (rr < N) v = __ldg((const float4*)(A + (size_t)rr * 128 + k4));
        sAT[(k4 + 0) * 68 + r] = v.x;
        sAT[(k4 + 1) * 68 + r] = v.y;
        sAT[(k4 + 2) * 68 + r] = v.z;
        sAT[(k4 + 3) * 68 + r] = v.w;
    }
    __syncthreads();

    int cg = (tid & 15) << 2;   // cols [cg, cg+4) of 64 (only <40 real)
    int rg = (tid >> 4) << 2;   // rows [rg, rg+4)
    float acc[4][4];
    #pragma unroll
    for (int i = 0; i < 4; i++)
        #pragma unroll
        for (int j = 0; j < 4; j++) acc[i][j] = 0.f;

    #pragma unroll 8
    for (int k = 0; k < 128; k++) {
        float4 wv = *(const float4*)(sW + k * 64 + cg);
        float4 av = *(const float4*)(sAT + k * 68 + rg);
        float ar[4] = {av.x, av.y, av.z, av.w};
        #pragma unroll
        for (int i = 0; i < 4; i++) {
            acc[i][0] = fmaf(ar[i], wv.x, acc[i][0]);
            acc[i][1] = fmaf(ar[i], wv.y, acc[i][1]);
            acc[i][2] = fmaf(ar[i], wv.z, acc[i][2]);
            acc[i][3] = fmaf(ar[i], wv.w, acc[i][3]);
        }
    }

    #pragma unroll
    for (int i = 0; i < 4; i++) {
        int rr = row0 + rg + i;
        if (rr < N) {
            float sc = __ldg(&g_din_is[rr]);
            #pragma unroll
            for (int j = 0; j < 4; j++) {
                int c = cg + j;
                if (c < 40)
                    sOut[(rg + i) * 40 + c] = fmaf(acc[i][j], sc, __ldg(b3 + c));
            }
        }
    }
    __syncthreads();

    if (tid < 64) {
        int rr = row0 + tid;
        if (rr < N) {
            const float* rp = sOut + tid * 40;
            float m = -1e30f;
            #pragma unroll
            for (int c = 0; c < 40; c++) m = fmaxf(m, rp[c]);
            float s = 0.f;
            #pragma unroll
            for (int c = 0; c < 40; c++) s += expf(rp[c] - m);
            float lse = m + logf(s);
            float* op = out + (size_t)rr * 40;
            #pragma unroll
            for (int c = 0; c < 40; c++) op[c] = rp[c] - lse;
        }
    }
}

// ---------------------------------------------------------------------------
extern "C" void kernel_launch(void* const* d_in, const int* in_sizes, int n_in,
                              void* d_out, int out_size)
{
    const float* x   = (const float*)d_in[0];
    const int*   src = (const int*)d_in[1];
    const int*   dst = (const int*)d_in[2];
    const float* W1  = (const float*)d_in[3];
    const float* b1  = (const float*)d_in[4];
    const float* g1  = (const float*)d_in[5];
    const float* be1 = (const float*)d_in[6];
    const float* W2  = (const float*)d_in[7];
    const float* b2  = (const float*)d_in[8];
    const float* g2  = (const float*)d_in[9];
    const float* be2 = (const float*)d_in[10];
    const float* W3  = (const float*)d_in[11];
    const float* b3  = (const float*)d_in[12];

    int N = in_sizes[0] / DD;
    int E = in_sizes[1];
    float* out = (float*)d_out;

    float *bufA, *bufB;
    cudaGetSymbolAddress((void**)&bufA, g_bufA);
    cudaGetSymbolAddress((void**)&bufB, g_bufB);

    cudaFuncSetAttribute(gemm128_kernel,
                         cudaFuncAttributeMaxDynamicSharedMemorySize, SMEM128);
    cudaFuncSetAttribute(gemm40_kernel,
                         cudaFuncAttributeMaxDynamicSharedMemorySize, SMEM40);

    int n4      = N * 32;             // float4 count of an N x 128 buffer
    int egrid   = (E + 7) / 8;        // 8 warps (edges) per 256-thread block
    int ngrid   = (N + 255) / 256;
    int ggrid   = (N + 63) / 64;
    float invN  = 1.0f / (float)N;

    // degrees
    zero_deg_kernel<<<ngrid, 256>>>(N);
    deg_count_kernel<<<(E + 255) / 256, 256>>>(src, dst, E);
    deg_inv_kernel<<<ngrid, 256>>>(N);

    // layer 1
    zero_f4_kernel<<<1024, 256>>>((float4*)bufA, n4);
    prop_kernel<0><<<egrid, 256>>>((const float4*)x, src, dst, bufA, E);
    gemm128_kernel<<<ggrid, 256, SMEM128>>>(bufA, W1, b1, bufB, N);
    bn_stats_kernel<<<1024, 128>>>(bufB, N);
    bn_finalize_kernel<<<1, 128>>>(g1, be1, invN);

    // layer 2
    zero_f4_kernel<<<1024, 256>>>((float4*)bufA, n4);
    prop_kernel<1><<<egrid, 256>>>((const float4*)bufB, src, dst, bufA, E);
    gemm128_kernel<<<ggrid, 256, SMEM128>>>(bufA, W2, b2, bufB, N);
    bn_stats_kernel<<<1024, 128>>>(bufB, N);
    bn_finalize_kernel<<<1, 128>>>(g2, be2, invN);

    // layer 3 + log_softmax
    zero_f4_kernel<<<1024, 256>>>((float4*)bufA, n4);
    prop_kernel<1><<<egrid, 256>>>((const float4*)bufB, src, dst, bufA, E);
    gemm40_kernel<<<ggrid, 256, SMEM40>>>(bufA, W3, b3, out, N);
}

// round 5
// speedup vs baseline: 1.2802x; 1.2802x over previous
#include <cuda_runtime.h>

// ---------------------------------------------------------------------------
// GCN: 3x (GraphConv norm='both') with BN+ReLU between, log_softmax at end.
// N=100000 nodes, E=1.6M edges, D=128, C=40.
//
// Round-4 pipeline (graph-capturable, alloc-free):
//   degrees (int atomics) -> deg^-1/2
//   CSR-by-dst build: 1-block prefix scan of deg_in + atomic-cursor fill
//   L1: prop_csr (warp/node register accumulate, no atomics);
//       gemm128 (+din,+b1, fused BN stats); bn_finalize
//   L2: prop_csr with fused BN+ReLU on gather; gemm128 (fused stats); finalize
//   L3: prop_csr with fused BN+ReLU; gemm40 + log_softmax fused
// ---------------------------------------------------------------------------

#define NMAX 100096
#define EMAX 1600000
#define DD 128

__device__ float g_bufA[(size_t)NMAX * DD];   // agg buffer
__device__ float g_bufB[(size_t)NMAX * DD];   // gemm output / next layer input
__device__ float g_dout_is[NMAX];
__device__ float g_din_is[NMAX];
__device__ int   g_deg_out[NMAX];
__device__ int   g_deg_in[NMAX];
__device__ int   g_row_off[NMAX + 1];
__device__ int   g_cursor[NMAX];
__device__ int   g_csr_src[EMAX];
__device__ float g_colsum[DD];  // zero-init; bn_finalize re-zeros after use
__device__ float g_colsq[DD];
__device__ float g_bn_a[DD];
__device__ float g_bn_b[DD];

// ---------------------------------------------------------------------------
__global__ void zero_deg_kernel(int n) {
    int i = blockIdx.x * blockDim.x + threadIdx.x;
    if (i < n) { g_deg_out[i] = 0; g_deg_in[i] = 0; }
}

__global__ void deg_count_kernel(const int* __restrict__ src,
                                 const int* __restrict__ dst, int E) {
    int i = blockIdx.x * blockDim.x + threadIdx.x;
    if (i < E) {
        atomicAdd(&g_deg_out[src[i]], 1);
        atomicAdd(&g_deg_in[dst[i]], 1);
    }
}

__global__ void deg_inv_kernel(int n) {
    int i = blockIdx.x * blockDim.x + threadIdx.x;
    if (i < n) {
        g_dout_is[i] = rsqrtf(fmaxf((float)g_deg_out[i], 1.f));
        g_din_is[i]  = rsqrtf(fmaxf((float)g_deg_in[i], 1.f));
    }
}

// ---------------------------------------------------------------------------
// Single-block exclusive prefix scan of deg_in -> row_off (+ cursor copy).
// 1024 threads, each owns a contiguous chunk of ceil(N/1024) nodes.
// ---------------------------------------------------------------------------
__global__ void __launch_bounds__(1024) scan_kernel(int N) {
    __shared__ int sdata[1024];
    int t = threadIdx.x;
    int chunk = (N + 1023) >> 10;
    int lo = t * chunk;
    int hi = min(lo + chunk, N);

    int s = 0;
    for (int i = lo; i < hi; i++) s += g_deg_in[i];
    sdata[t] = s;
    __syncthreads();
    // Hillis-Steele inclusive scan over 1024 entries
    #pragma unroll
    for (int off = 1; off < 1024; off <<= 1) {
        int v = (t >= off) ? sdata[t - off] : 0;
        __syncthreads();
        sdata[t] += v;
        __syncthreads();
    }
    int run = sdata[t] - s;  // exclusive prefix of this chunk
    for (int i = lo; i < hi; i++) {
        g_row_off[i] = run;
        g_cursor[i]  = run;
        run += g_deg_in[i];
    }
    if (t == 1023) g_row_off[N] = run;  // == E
}

__global__ void csr_fill_kernel(const int* __restrict__ src,
                                const int* __restrict__ dst, int E) {
    int i = blockIdx.x * blockDim.x + threadIdx.x;
    if (i < E) {
        int pos = atomicAdd(&g_cursor[dst[i]], 1);
        g_csr_src[pos] = src[i];
    }
}

// ---------------------------------------------------------------------------
// CSR propagation: one warp per dst node. Lane l owns features [4l, 4l+4).
// acc = sum over in-edges of (USE_BN ? relu(in*a+b) : in)[s] * dout_is[s].
// Register accumulation, streaming float4 store, zero atomics.
// ---------------------------------------------------------------------------
template <int USE_BN>
__global__ void __launch_bounds__(256) prop_csr_kernel(
    const float4* __restrict__ in, float* __restrict__ out, int N)
{
    int node = blockIdx.x * 8 + (threadIdx.x >> 5);
    if (node >= N) return;
    int lane = threadIdx.x & 31;
    int start = __ldg(&g_row_off[node]);
    int end   = __ldg(&g_row_off[node + 1]);

    float4 bnA, bnB;
    if (USE_BN) {
        bnA = __ldg(((const float4*)g_bn_a) + lane);
        bnB = __ldg(((const float4*)g_bn_b) + lane);
    }

    float4 acc = make_float4(0.f, 0.f, 0.f, 0.f);
    for (int base = start; base < end; base += 32) {
        int n = min(32, end - base);
        int s = 0; float sc = 0.f;
        if (lane < n) {
            s  = __ldg(g_csr_src + base + lane);
            sc = __ldg(&g_dout_is[s]);
        }
        for (int j = 0; j < n; j++) {
            int   sj  = __shfl_sync(0xffffffffu, s, j);
            float scj = __shfl_sync(0xffffffffu, sc, j);
            float4 v = __ldg(in + (size_t)sj * 32 + lane);
            if (USE_BN) {
                v.x = fmaxf(fmaf(v.x, bnA.x, bnB.x), 0.f);
                v.y = fmaxf(fmaf(v.y, bnA.y, bnB.y), 0.f);
                v.z = fmaxf(fmaf(v.z, bnA.z, bnB.z), 0.f);
                v.w = fmaxf(fmaf(v.w, bnA.w, bnB.w), 0.f);
            }
            acc.x = fmaf(v.x, scj, acc.x);
            acc.y = fmaf(v.y, scj, acc.y);
            acc.z = fmaf(v.z, scj, acc.z);
            acc.w = fmaf(v.w, scj, acc.w);
        }
    }
    ((float4*)out)[(size_t)node * 32 + lane] = acc;
}

// ---------------------------------------------------------------------------
// GEMM: out[r,c] = din_is[r] * (A[r,:] @ W[:,c]) + bias[c], D=128 square,
// with BN column stats (sum, sumsq of out) fused into the epilogue.
// Block: 64 rows x 128 cols, 256 threads, 8 rows x 4 cols per thread.
// ---------------------------------------------------------------------------
#define SMEM128 ((128 * 128 + 128 * 68 + 256) * 4)

__global__ void __launch_bounds__(256) gemm128_kernel(
    const float* __restrict__ A, const float* __restrict__ W,
    const float* __restrict__ bias, float* __restrict__ out, int N)
{
    extern __shared__ float sm[];
    float* sW   = sm;                        // [k][c], 128*128
    float* sAT  = sm + 128 * 128;            // [k][r], leading dim 68
    float* sSum = sAT + 128 * 68;            // [128]
    float* sSq  = sSum + 128;                // [128]
    int tid  = threadIdx.x;
    int row0 = blockIdx.x * 64;

    if (tid < 128) { sSum[tid] = 0.f; sSq[tid] = 0.f; }

    {
        const float4* W4 = (const float4*)W;
        float4* sW4 = (float4*)sW;
        #pragma unroll
        for (int i = 0; i < 16; i++) sW4[tid + i * 256] = __ldg(W4 + tid + i * 256);
    }
    #pragma unroll
    for (int ii = 0; ii < 8; ii++) {
        int i  = tid + ii * 256;           // 2048 float4 total
        int r  = i >> 5;
        int k4 = (i & 31) << 2;
        int rr = row0 + r;
        float4 v = make_float4(0.f, 0.f, 0.f, 0.f);
        if (rr < N) v = __ldg((const float4*)(A + (size_t)rr * 128 + k4));
        sAT[(k4 + 0) * 68 + r] = v.x;
        sAT[(k4 + 1) * 68 + r] = v.y;
        sAT[(k4 + 2) * 68 + r] = v.z;
        sAT[(k4 + 3) * 68 + r] = v.w;
    }
    __syncthreads();

    int cg = (tid & 31) << 2;   // cols [cg, cg+4)
    int rg = (tid >> 5) << 3;   // rows [rg, rg+8) (warp-uniform -> LDS broadcast)
    float acc[8][4];
    #pragma unroll
    for (int i = 0; i < 8; i++)
        #pragma unroll
        for (int j = 0; j < 4; j++) acc[i][j] = 0.f;

    #pragma unroll 8
    for (int k = 0; k < 128; k++) {
        float4 wv = *(const float4*)(sW + k * 128 + cg);
        float4 a0 = *(const float4*)(sAT + k * 68 + rg);
        float4 a1 = *(const float4*)(sAT + k * 68 + rg + 4);
        float ar[8] = {a0.x, a0.y, a0.z, a0.w, a1.x, a1.y, a1.z, a1.w};
        #pragma unroll
        for (int i = 0; i < 8; i++) {
            acc[i][0] = fmaf(ar[i], wv.x, acc[i][0]);
            acc[i][1] = fmaf(ar[i], wv.y, acc[i][1]);
            acc[i][2] = fmaf(ar[i], wv.z, acc[i][2]);
            acc[i][3] = fmaf(ar[i], wv.w, acc[i][3]);
        }
    }

    float4 bv = __ldg((const float4*)(bias + cg));
    float csum[4] = {0.f, 0.f, 0.f, 0.f};
    float csq[4]  = {0.f, 0.f, 0.f, 0.f};
    #pragma unroll
    for (int i = 0; i < 8; i++) {
        int rr = row0 + rg + i;
        if (rr < N) {
            float sc = __ldg(&g_din_is[rr]);
            float4 o;
            o.x = fmaf(acc[i][0], sc, bv.x);
            o.y = fmaf(acc[i][1], sc, bv.y);
            o.z = fmaf(acc[i][2], sc, bv.z);
            o.w = fmaf(acc[i][3], sc, bv.w);
            csum[0] += o.x; csq[0] = fmaf(o.x, o.x, csq[0]);
            csum[1] += o.y; csq[1] = fmaf(o.y, o.y, csq[1]);
            csum[2] += o.z; csq[2] = fmaf(o.z, o.z, csq[2]);
            csum[3] += o.w; csq[3] = fmaf(o.w, o.w, csq[3]);
            *(float4*)(out + (size_t)rr * 128 + cg) = o;
        }
    }
    #pragma unroll
    for (int j = 0; j < 4; j++) {
        atomicAdd(&sSum[cg + j], csum[j]);
        atomicAdd(&sSq[cg + j],  csq[j]);
    }
    __syncthreads();
    if (tid < 128) {
        atomicAdd(&g_colsum[tid], sSum[tid]);
        atomicAdd(&g_colsq[tid],  sSq[tid]);
    }
}

__global__ void bn_finalize_kernel(const float* __restrict__ g,
                                   const float* __restrict__ be, float invN) {
    int c = threadIdx.x;  // 128 threads
    float mu  = g_colsum[c] * invN;
    float var = fmaf(-mu, mu, g_colsq[c] * invN);
    float a   = __ldg(g + c) * rsqrtf(var + 1e-5f);
    g_bn_a[c] = a;
    g_bn_b[c] = fmaf(-mu, a, __ldg(be + c));
    g_colsum[c] = 0.f;  // reset for next BN / next launch
    g_colsq[c]  = 0.f;
}

// ---------------------------------------------------------------------------
// Final layer: out = log_softmax(din_is[r] * (A[r,:] @ W3) + b3), C=40.
// Block: 64 rows. W3 zero-padded to 128x64 in shared. 4x4 per thread.
// ---------------------------------------------------------------------------
#define SMEM40 ((128 * 64 + 128 * 68 + 64 * 40) * 4)

__global__ void __launch_bounds__(256) gemm40_kernel(
    const float* __restrict__ A, const float* __restrict__ W3,
    const float* __restrict__ b3, float* __restrict__ out, int N)
{
    extern __shared__ float sm[];
    float* sW   = sm;                       // [k][c] padded to 64 cols
    float* sAT  = sm + 128 * 64;            // [k][r] ld 68
    float* sOut = sAT + 128 * 68;           // [64][40]
    int tid  = threadIdx.x;
    int row0 = blockIdx.x * 64;

    for (int i = tid; i < 128 * 64; i += 256) sW[i] = 0.f;
    __syncthreads();
    for (int i = tid; i < 128 * 40; i += 256) {
        int k = i / 40, c = i - k * 40;
        sW[k * 64 + c] = __ldg(W3 + i);
    }
    #pragma unroll
    for (int ii = 0; ii < 8; ii++) {
        int i  = tid + ii * 256;
        int r  = i >> 5;
        int k4 = (i & 31) << 2;
        int rr = row0 + r;
        float4 v = make_float4(0.f, 0.f, 0.f, 0.f);
        if (rr < N) v = __ldg((const float4*)(A + (size_t)rr * 128 + k4));
        sAT[(k4 + 0) * 68 + r] = v.x;
        sAT[(k4 + 1) * 68 + r] = v.y;
        sAT[(k4 + 2) * 68 + r] = v.z;
        sAT[(k4 + 3) * 68 + r] = v.w;
    }
    __syncthreads();

    int cg = (tid & 15) << 2;   // cols [cg, cg+4) of 64 (only <40 real)
    int rg = (tid >> 4) << 2;   // rows [rg, rg+4)
    float acc[4][4];
    #pragma unroll
    for (int i = 0; i < 4; i++)
        #pragma unroll
        for (int j = 0; j < 4; j++) acc[i][j] = 0.f;

    #pragma unroll 8
    for (int k = 0; k < 128; k++) {
        float4 wv = *(const float4*)(sW + k * 64 + cg);
        float4 av = *(const float4*)(sAT + k * 68 + rg);
        float ar[4] = {av.x, av.y, av.z, av.w};
        #pragma unroll
        for (int i = 0; i < 4; i++) {
            acc[i][0] = fmaf(ar[i], wv.x, acc[i][0]);
            acc[i][1] = fmaf(ar[i], wv.y, acc[i][1]);
            acc[i][2] = fmaf(ar[i], wv.z, acc[i][2]);
            acc[i][3] = fmaf(ar[i], wv.w, acc[i][3]);
        }
    }

    #pragma unroll
    for (int i = 0; i < 4; i++) {
        int rr = row0 + rg + i;
        if (rr < N) {
            float sc = __ldg(&g_din_is[rr]);
            #pragma unroll
            for (int j = 0; j < 4; j++) {
                int c = cg + j;
                if (c < 40)
                    sOut[(rg + i) * 40 + c] = fmaf(acc[i][j], sc, __ldg(b3 + c));
            }
        }
    }
    __syncthreads();

    if (tid < 64) {
        int rr = row0 + tid;
        if (rr < N) {
            const float* rp = sOut + tid * 40;
            float m = -1e30f;
            #pragma unroll
            for (int c = 0; c < 40; c++) m = fmaxf(m, rp[c]);
            float s = 0.f;
            #pragma unroll
            for (int c = 0; c < 40; c++) s += expf(rp[c] - m);
            float lse = m + logf(s);
            float* op = out + (size_t)rr * 40;
            #pragma unroll
            for (int c = 0; c < 40; c++) op[c] = rp[c] - lse;
        }
    }
}

// ---------------------------------------------------------------------------
extern "C" void kernel_launch(void* const* d_in, const int* in_sizes, int n_in,
                              void* d_out, int out_size)
{
    const float* x   = (const float*)d_in[0];
    const int*   src = (const int*)d_in[1];
    const int*   dst = (const int*)d_in[2];
    const float* W1  = (const float*)d_in[3];
    const float* b1  = (const float*)d_in[4];
    const float* g1  = (const float*)d_in[5];
    const float* be1 = (const float*)d_in[6];
    const float* W2  = (const float*)d_in[7];
    const float* b2  = (const float*)d_in[8];
    const float* g2  = (const float*)d_in[9];
    const float* be2 = (const float*)d_in[10];
    const float* W3  = (const float*)d_in[11];
    const float* b3  = (const float*)d_in[12];

    int N = in_sizes[0] / DD;
    int E = in_sizes[1];
    float* out = (float*)d_out;

    float *bufA, *bufB;
    cudaGetSymbolAddress((void**)&bufA, g_bufA);
    cudaGetSymbolAddress((void**)&bufB, g_bufB);

    cudaFuncSetAttribute(gemm128_kernel,
                         cudaFuncAttributeMaxDynamicSharedMemorySize, SMEM128);
    cudaFuncSetAttribute(gemm40_kernel,
                         cudaFuncAttributeMaxDynamicSharedMemorySize, SMEM40);

    int ngrid  = (N + 255) / 256;
    int egrid  = (E + 255) / 256;
    int pgrid  = (N + 7) / 8;      // 8 warps (nodes) per 256-thread block
    int ggrid  = (N + 63) / 64;
    float invN = 1.0f / (float)N;

    // degrees + CSR-by-dst
    zero_deg_kernel<<<ngrid, 256>>>(N);
    deg_count_kernel<<<egrid, 256>>>(src, dst, E);
    deg_inv_kernel<<<ngrid, 256>>>(N);
    scan_kernel<<<1, 1024>>>(N);
    csr_fill_kernel<<<egrid, 256>>>(src, dst, E);

    // layer 1
    prop_csr_kernel<0><<<pgrid, 256>>>((const float4*)x, bufA, N);
    gemm128_kernel<<<ggrid, 256, SMEM128>>>(bufA, W1, b1, bufB, N);
    bn_finalize_kernel<<<1, 128>>>(g1, be1, invN);

    // layer 2
    prop_csr_kernel<1><<<pgrid, 256>>>((const float4*)bufB, bufA, N);
    gemm128_kernel<<<ggrid, 256, SMEM128>>>(bufA, W2, b2, bufB, N);
    bn_finalize_kernel<<<1, 128>>>(g2, be2, invN);

    // layer 3 + log_softmax
    prop_csr_kernel<1><<<pgrid, 256>>>((const float4*)bufB, bufA, N);
    gemm40_kernel<<<ggrid, 256, SMEM40>>>(bufA, W3, b3, out, N);
}

// round 6
// speedup vs baseline: 1.6492x; 1.2882x over previous
#include <cuda_runtime.h>

// ---------------------------------------------------------------------------
// GCN: 3x (GraphConv norm='both') with BN+ReLU between, log_softmax at end.
// N=100000 nodes, E=1.6M edges, D=128, C=40.
//
// Round-6 pipeline (graph-capturable, alloc-free):
//   degrees (int atomics) -> deg^-1/2
//   CSR-by-dst build: parallel 3-phase scan (warp chunk sums -> 1-block scan
//     of 1024 partials -> warp-scan fill) + atomic-cursor fill
//   L1: prop_csr (warp/node register accumulate, no atomics);
//       gemm128 (f32x2 packed FMA, +din,+b1, fused BN stats); bn_finalize
//   L2: prop_csr with fused BN+ReLU on gather; gemm128 (fused stats); finalize
//   L3: prop_csr with fused BN+ReLU; gemm40 + log_softmax fused
// ---------------------------------------------------------------------------

#define NMAX 100096
#define EMAX 1600000
#define DD 128
#define CHUNKS 1024

__device__ float g_bufA[(size_t)NMAX * DD];   // agg buffer
__device__ float g_bufB[(size_t)NMAX * DD];   // gemm output / next layer input
__device__ float g_dout_is[NMAX];
__device__ float g_din_is[NMAX];
__device__ int   g_deg_out[NMAX];
__device__ int   g_deg_in[NMAX];
__device__ int   g_row_off[NMAX + 1];
__device__ int   g_cursor[NMAX];
__device__ int   g_csr_src[EMAX];
__device__ int   g_chunk_sum[CHUNKS];
__device__ float g_colsum[DD];  // zero-init; bn_finalize re-zeros after use
__device__ float g_colsq[DD];
__device__ float g_bn_a[DD];
__device__ float g_bn_b[DD];

// packed f32x2 helpers (sm_100+: lowers to FFMA2 / 64-bit regs)
#define FMA_F32X2(d, a, b, c) \
    asm("fma.rn.f32x2 %0, %1, %2, %3;" \
        : "=l"(d) : "l"(a), "l"(b), "l"(c))
#define PACKF2(out, lo, hi) \
    asm("mov.b64 %0, {%1, %2};" \
        : "=l"(out) : "r"(__float_as_uint(lo)), "r"(__float_as_uint(hi)))
#define UNPACKF2(lo, hi, in) \
    do { unsigned int _ulo, _uhi; \
         asm("mov.b64 {%0, %1}, %2;" : "=r"(_ulo), "=r"(_uhi) : "l"(in)); \
         lo = __uint_as_float(_ulo); hi = __uint_as_float(_uhi); } while (0)

// ---------------------------------------------------------------------------
__global__ void zero_deg_kernel(int n) {
    int i = blockIdx.x * blockDim.x + threadIdx.x;
    if (i < n) { g_deg_out[i] = 0; g_deg_in[i] = 0; }
}

__global__ void deg_count_kernel(const int* __restrict__ src,
                                 const int* __restrict__ dst, int E) {
    int i = blockIdx.x * blockDim.x + threadIdx.x;
    if (i < E) {
        atomicAdd(&g_deg_out[src[i]], 1);
        atomicAdd(&g_deg_in[dst[i]], 1);
    }
}

__global__ void deg_inv_kernel(int n) {
    int i = blockIdx.x * blockDim.x + threadIdx.x;
    if (i < n) {
        g_dout_is[i] = rsqrtf(fmaxf((float)g_deg_out[i], 1.f));
        g_din_is[i]  = rsqrtf(fmaxf((float)g_deg_in[i], 1.f));
    }
}

// ---------------------------------------------------------------------------
// Parallel exclusive scan of deg_in -> row_off (3 phases, full-chip).
// ---------------------------------------------------------------------------
__global__ void __launch_bounds__(256) chunk_sum_kernel(int N, int chunk) {
    int w = blockIdx.x * 8 + (threadIdx.x >> 5);
    if (w >= CHUNKS) return;
    int lane = threadIdx.x & 31;
    int lo = w * chunk, hi = min(lo + chunk, N);
    int s = 0;
    for (int i = lo + lane; i < hi; i += 32) s += g_deg_in[i];
    #pragma unroll
    for (int off = 16; off; off >>= 1)
        s += __shfl_down_sync(0xffffffffu, s, off);
    if (lane == 0) g_chunk_sum[w] = s;
}

__global__ void __launch_bounds__(1024) scan_chunks_kernel(int N) {
    __shared__ int sdata[1024];
    int t = threadIdx.x;
    int v = g_chunk_sum[t];
    sdata[t] = v;
    __syncthreads();
    #pragma unroll
    for (int off = 1; off < 1024; off <<= 1) {
        int u = (t >= off) ? sdata[t - off] : 0;
        __syncthreads();
        sdata[t] += u;
        __syncthreads();
    }
    g_chunk_sum[t] = sdata[t] - v;          // exclusive prefix per chunk
    if (t == 1023) g_row_off[N] = sdata[1023];
}

__global__ void __launch_bounds__(256) fill_off_kernel(int N, int chunk) {
    int w = blockIdx.x * 8 + (threadIdx.x >> 5);
    if (w >= CHUNKS) return;
    int lane = threadIdx.x & 31;
    int lo = w * chunk, hi = min(lo + chunk, N);
    int run = g_chunk_sum[w];
    for (int base = lo; base < hi; base += 32) {
        int i = base + lane;
        int v = (i < hi) ? __ldg(&g_deg_in[i]) : 0;
        int incl = v;
        #pragma unroll
        for (int off = 1; off < 32; off <<= 1) {
            int t = __shfl_up_sync(0xffffffffu, incl, off);
            if (lane >= off) incl += t;
        }
        if (i < hi) {
            int off_i = run + incl - v;
            g_row_off[i] = off_i;
            g_cursor[i]  = off_i;
        }
        run += __shfl_sync(0xffffffffu, incl, 31);
    }
}

__global__ void csr_fill_kernel(const int* __restrict__ src,
                                const int* __restrict__ dst, int E) {
    int i = blockIdx.x * blockDim.x + threadIdx.x;
    if (i < E) {
        int pos = atomicAdd(&g_cursor[dst[i]], 1);
        g_csr_src[pos] = src[i];
    }
}

// ---------------------------------------------------------------------------
// CSR propagation: one warp per dst node. Lane l owns features [4l, 4l+4).
// acc = sum over in-edges of (USE_BN ? relu(in*a+b) : in)[s] * dout_is[s].
// Register accumulation, streaming float4 store, zero atomics.
// ---------------------------------------------------------------------------
template <int USE_BN>
__global__ void __launch_bounds__(256) prop_csr_kernel(
    const float4* __restrict__ in, float* __restrict__ out, int N)
{
    int node = blockIdx.x * 8 + (threadIdx.x >> 5);
    if (node >= N) return;
    int lane = threadIdx.x & 31;
    int start = __ldg(&g_row_off[node]);
    int end   = __ldg(&g_row_off[node + 1]);

    float4 bnA, bnB;
    if (USE_BN) {
        bnA = __ldg(((const float4*)g_bn_a) + lane);
        bnB = __ldg(((const float4*)g_bn_b) + lane);
    }

    float4 acc = make_float4(0.f, 0.f, 0.f, 0.f);
    for (int base = start; base < end; base += 32) {
        int n = min(32, end - base);
        int s = 0; float sc = 0.f;
        if (lane < n) {
            s  = __ldg(g_csr_src + base + lane);
            sc = __ldg(&g_dout_is[s]);
        }
        for (int j = 0; j < n; j++) {
            int   sj  = __shfl_sync(0xffffffffu, s, j);
            float scj = __shfl_sync(0xffffffffu, sc, j);
            float4 v = __ldg(in + (size_t)sj * 32 + lane);
            if (USE_BN) {
                v.x = fmaxf(fmaf(v.x, bnA.x, bnB.x), 0.f);
                v.y = fmaxf(fmaf(v.y, bnA.y, bnB.y), 0.f);
                v.z = fmaxf(fmaf(v.z, bnA.z, bnB.z), 0.f);
                v.w = fmaxf(fmaf(v.w, bnA.w, bnB.w), 0.f);
            }
            acc.x = fmaf(v.x, scj, acc.x);
            acc.y = fmaf(v.y, scj, acc.y);
            acc.z = fmaf(v.z, scj, acc.z);
            acc.w = fmaf(v.w, scj, acc.w);
        }
    }
    ((float4*)out)[(size_t)node * 32 + lane] = acc;
}

// ---------------------------------------------------------------------------
// GEMM: out[r,c] = din_is[r] * (A[r,:] @ W[:,c]) + bias[c], D=128 square,
// with BN column stats (sum, sumsq of out) fused into the epilogue.
// Block: 64 rows x 128 cols, 256 threads, 8 rows x 4 cols per thread.
// Inner loop uses packed fma.rn.f32x2 over row pairs (adjacent rows in the
// transposed-A tile are contiguous -> 16B shared load = two f32x2 operands).
// ---------------------------------------------------------------------------
#define SMEM128 ((128 * 128 + 128 * 68 + 256) * 4)

__global__ void __launch_bounds__(256) gemm128_kernel(
    const float* __restrict__ A, const float* __restrict__ W,
    const float* __restrict__ bias, float* __restrict__ out, int N)
{
    extern __shared__ float sm[];
    float* sW   = sm;                        // [k][c], 128*128
    float* sAT  = sm + 128 * 128;            // [k][r], leading dim 68
    float* sSum = sAT + 128 * 68;            // [128]
    float* sSq  = sSum + 128;                // [128]
    int tid  = threadIdx.x;
    int row0 = blockIdx.x * 64;

    if (tid < 128) { sSum[tid] = 0.f; sSq[tid] = 0.f; }

    {
        const float4* W4 = (const float4*)W;
        float4* sW4 = (float4*)sW;
        #pragma unroll
        for (int i = 0; i < 16; i++) sW4[tid + i * 256] = __ldg(W4 + tid + i * 256);
    }
    #pragma unroll
    for (int ii = 0; ii < 8; ii++) {
        int i  = tid + ii * 256;           // 2048 float4 total
        int r  = i >> 5;
        int k4 = (i & 31) << 2;
        int rr = row0 + r;
        float4 v = make_float4(0.f, 0.f, 0.f, 0.f);
        if (rr < N) v = __ldg((const float4*)(A + (size_t)rr * 128 + k4));
        sAT[(k4 + 0) * 68 + r] = v.x;
        sAT[(k4 + 1) * 68 + r] = v.y;
        sAT[(k4 + 2) * 68 + r] = v.z;
        sAT[(k4 + 3) * 68 + r] = v.w;
    }
    __syncthreads();

    int cg = (tid & 31) << 2;   // cols [cg, cg+4)
    int rg = (tid >> 5) << 3;   // rows [rg, rg+8) (warp-uniform -> LDS broadcast)

    // accp[pr][j]: f32x2 accumulator for (row rg+2pr, row rg+2pr+1), col cg+j
    unsigned long long accp[4][4];
    #pragma unroll
    for (int pr = 0; pr < 4; pr++)
        #pragma unroll
        for (int j = 0; j < 4; j++) accp[pr][j] = 0ull;

    #pragma unroll 8
    for (int k = 0; k < 128; k++) {
        float4 wv = *(const float4*)(sW + k * 128 + cg);
        const ulonglong2* apt = (const ulonglong2*)(sAT + k * 68 + rg);
        ulonglong2 a01 = apt[0];          // rows (rg, rg+1), (rg+2, rg+3)
        ulonglong2 a23 = apt[1];          // rows (rg+4, rg+5), (rg+6, rg+7)
        unsigned long long ap[4] = {a01.x, a01.y, a23.x, a23.y};
        unsigned long long wd[4];
        PACKF2(wd[0], wv.x, wv.x);
        PACKF2(wd[1], wv.y, wv.y);
        PACKF2(wd[2], wv.z, wv.z);
        PACKF2(wd[3], wv.w, wv.w);
        #pragma unroll
        for (int pr = 0; pr < 4; pr++)
            #pragma unroll
            for (int j = 0; j < 4; j++)
                FMA_F32X2(accp[pr][j], ap[pr], wd[j], accp[pr][j]);
    }

    float acc[8][4];
    #pragma unroll
    for (int pr = 0; pr < 4; pr++)
        #pragma unroll
        for (int j = 0; j < 4; j++) {
            float lo, hi;
            UNPACKF2(lo, hi, accp[pr][j]);
            acc[2 * pr + 0][j] = lo;
            acc[2 * pr + 1][j] = hi;
        }

    float4 bv = __ldg((const float4*)(bias + cg));
    float csum[4] = {0.f, 0.f, 0.f, 0.f};
    float csq[4]  = {0.f, 0.f, 0.f, 0.f};
    #pragma unroll
    for (int i = 0; i < 8; i++) {
        int rr = row0 + rg + i;
        if (rr < N) {
            float sc = __ldg(&g_din_is[rr]);
            float4 o;
            o.x = fmaf(acc[i][0], sc, bv.x);
            o.y = fmaf(acc[i][1], sc, bv.y);
            o.z = fmaf(acc[i][2], sc, bv.z);
            o.w = fmaf(acc[i][3], sc, bv.w);
            csum[0] += o.x; csq[0] = fmaf(o.x, o.x, csq[0]);
            csum[1] += o.y; csq[1] = fmaf(o.y, o.y, csq[1]);
            csum[2] += o.z; csq[2] = fmaf(o.z, o.z, csq[2]);
            csum[3] += o.w; csq[3] = fmaf(o.w, o.w, csq[3]);
            *(float4*)(out + (size_t)rr * 128 + cg) = o;
        }
    }
    #pragma unroll
    for (int j = 0; j < 4; j++) {
        atomicAdd(&sSum[cg + j], csum[j]);
        atomicAdd(&sSq[cg + j],  csq[j]);
    }
    __syncthreads();
    if (tid < 128) {
        atomicAdd(&g_colsum[tid], sSum[tid]);
        atomicAdd(&g_colsq[tid],  sSq[tid]);
    }
}

__global__ void bn_finalize_kernel(const float* __restrict__ g,
                                   const float* __restrict__ be, float invN) {
    int c = threadIdx.x;  // 128 threads
    float mu  = g_colsum[c] * invN;
    float var = fmaf(-mu, mu, g_colsq[c] * invN);
    float a   = __ldg(g + c) * rsqrtf(var + 1e-5f);
    g_bn_a[c] = a;
    g_bn_b[c] = fmaf(-mu, a, __ldg(be + c));
    g_colsum[c] = 0.f;  // reset for next BN / next launch
    g_colsq[c]  = 0.f;
}

// ---------------------------------------------------------------------------
// Final layer: out = log_softmax(din_is[r] * (A[r,:] @ W3) + b3), C=40.
// Block: 64 rows. W3 zero-padded to 128x64 in shared. 4x4 per thread.
// ---------------------------------------------------------------------------
#define SMEM40 ((128 * 64 + 128 * 68 + 64 * 40) * 4)

__global__ void __launch_bounds__(256) gemm40_kernel(
    const float* __restrict__ A, const float* __restrict__ W3,
    const float* __restrict__ b3, float* __restrict__ out, int N)
{
    extern __shared__ float sm[];
    float* sW   = sm;                       // [k][c] padded to 64 cols
    float* sAT  = sm + 128 * 64;            // [k][r] ld 68
    float* sOut = sAT + 128 * 68;           // [64][40]
    int tid  = threadIdx.x;
    int row0 = blockIdx.x * 64;

    for (int i = tid; i < 128 * 64; i += 256) sW[i] = 0.f;
    __syncthreads();
    for (int i = tid; i < 128 * 40; i += 256) {
        int k = i / 40, c = i - k * 40;
        sW[k * 64 + c] = __ldg(W3 + i);
    }
    #pragma unroll
    for (int ii = 0; ii < 8; ii++) {
        int i  = tid + ii * 256;
        int r  = i >> 5;
        int k4 = (i & 31) << 2;
        int rr = row0 + r;
        float4 v = make_float4(0.f, 0.f, 0.f, 0.f);
        if (rr < N) v = __ldg((const float4*)(A + (size_t)rr * 128 + k4));
        sAT[(k4 + 0) * 68 + r] = v.x;
        sAT[(k4 + 1) * 68 + r] = v.y;
        sAT[(k4 + 2) * 68 + r] = v.z;
        sAT[(k4 + 3) * 68 + r] = v.w;
    }
    __syncthreads();

    int cg = (tid & 15) << 2;   // cols [cg, cg+4) of 64 (only <40 real)
    int rg = (tid >> 4) << 2;   // rows [rg, rg+4)
    float acc[4][4];
    #pragma unroll
    for (int i = 0; i < 4; i++)
        #pragma unroll
        for (int j = 0; j < 4; j++) acc[i][j] = 0.f;

    #pragma unroll 8
    for (int k = 0; k < 128; k++) {
        float4 wv = *(const float4*)(sW + k * 64 + cg);
        float4 av = *(const float4*)(sAT + k * 68 + rg);
        float ar[4] = {av.x, av.y, av.z, av.w};
        #pragma unroll
        for (int i = 0; i < 4; i++) {
            acc[i][0] = fmaf(ar[i], wv.x, acc[i][0]);
            acc[i][1] = fmaf(ar[i], wv.y, acc[i][1]);
            acc[i][2] = fmaf(ar[i], wv.z, acc[i][2]);
            acc[i][3] = fmaf(ar[i], wv.w, acc[i][3]);
        }
    }

    #pragma unroll
    for (int i = 0; i < 4; i++) {
        int rr = row0 + rg + i;
        if (rr < N) {
            float sc = __ldg(&g_din_is[rr]);
            #pragma unroll
            for (int j = 0; j < 4; j++) {
                int c = cg + j;
                if (c < 40)
                    sOut[(rg + i) * 40 + c] = fmaf(acc[i][j], sc, __ldg(b3 + c));
            }
        }
    }
    __syncthreads();

    if (tid < 64) {
        int rr = row0 + tid;
        if (rr < N) {
            const float* rp = sOut + tid * 40;
            float m = -1e30f;
            #pragma unroll
            for (int c = 0; c < 40; c++) m = fmaxf(m, rp[c]);
            float s = 0.f;
            #pragma unroll
            for (int c = 0; c < 40; c++) s += expf(rp[c] - m);
            float lse = m + logf(s);
            float* op = out + (size_t)rr * 40;
            #pragma unroll
            for (int c = 0; c < 40; c++) op[c] = rp[c] - lse;
        }
    }
}

// ---------------------------------------------------------------------------
extern "C" void kernel_launch(void* const* d_in, const int* in_sizes, int n_in,
                              void* d_out, int out_size)
{
    const float* x   = (const float*)d_in[0];
    const int*   src = (const int*)d_in[1];
    const int*   dst = (const int*)d_in[2];
    const float* W1  = (const float*)d_in[3];
    const float* b1  = (const float*)d_in[4];
    const float* g1  = (const float*)d_in[5];
    const float* be1 = (const float*)d_in[6];
    const float* W2  = (const float*)d_in[7];
    const float* b2  = (const float*)d_in[8];
    const float* g2  = (const float*)d_in[9];
    const float* be2 = (const float*)d_in[10];
    const float* W3  = (const float*)d_in[11];
    const float* b3  = (const float*)d_in[12];

    int N = in_sizes[0] / DD;
    int E = in_sizes[1];
    float* out = (float*)d_out;

    float *bufA, *bufB;
    cudaGetSymbolAddress((void**)&bufA, g_bufA);
    cudaGetSymbolAddress((void**)&bufB, g_bufB);

    cudaFuncSetAttribute(gemm128_kernel,
                         cudaFuncAttributeMaxDynamicSharedMemorySize, SMEM128);
    cudaFuncSetAttribute(gemm40_kernel,
                         cudaFuncAttributeMaxDynamicSharedMemorySize, SMEM40);

    int ngrid  = (N + 255) / 256;
    int egrid  = (E + 255) / 256;
    int pgrid  = (N + 7) / 8;      // 8 warps (nodes) per 256-thread block
    int ggrid  = (N + 63) / 64;
    int chunk  = (N + CHUNKS - 1) / CHUNKS;
    float invN = 1.0f / (float)N;

    // degrees + CSR-by-dst
    zero_deg_kernel<<<ngrid, 256>>>(N);
    deg_count_kernel<<<egrid, 256>>>(src, dst, E);
    deg_inv_kernel<<<ngrid, 256>>>(N);
    chunk_sum_kernel<<<CHUNKS / 8, 256>>>(N, chunk);
    scan_chunks_kernel<<<1, 1024>>>(N);
    fill_off_kernel<<<CHUNKS / 8, 256>>>(N, chunk);
    csr_fill_kernel<<<egrid, 256>>>(src, dst, E);

    // layer 1
    prop_csr_kernel<0><<<pgrid, 256>>>((const float4*)x, bufA, N);
    gemm128_kernel<<<ggrid, 256, SMEM128>>>(bufA, W1, b1, bufB, N);
    bn_finalize_kernel<<<1, 128>>>(g1, be1, invN);

    // layer 2
    prop_csr_kernel<1><<<pgrid, 256>>>((const float4*)bufB, bufA, N);
    gemm128_kernel<<<ggrid, 256, SMEM128>>>(bufA, W2, b2, bufB, N);
    bn_finalize_kernel<<<1, 128>>>(g2, be2, invN);

    // layer 3 + log_softmax
    prop_csr_kernel<1><<<pgrid, 256>>>((const float4*)bufB, bufA, N);
    gemm40_kernel<<<ggrid, 256, SMEM40>>>(bufA, W3, b3, out, N);
}

// round 7
// speedup vs baseline: 1.8340x; 1.1120x over previous
#include <cuda_runtime.h>

// ---------------------------------------------------------------------------
// GCN: 3x (GraphConv norm='both') with BN+ReLU between, log_softmax at end.
// N=100000 nodes, E=1.6M edges, D=128, C=40.
//
// Round-7 pipeline (graph-capturable, alloc-free):
//   degrees (int atomics) -> deg^-1/2
//   CSR-by-dst build: parallel 3-phase scan + atomic-cursor fill
//   L1: prop_csr (warp/node, MLP-4 pipelined gathers); gemm128 (f32x2,
//       fused BN stats); bn_finalize
//   L2: prop_csr with fused BN+ReLU; gemm128 (fused stats); bn_finalize
//   L3: gemm40pre (BN+ReLU on load, x@W3, dout scale) -> 40-wide prop
//       with fused bias + log_softmax (prop/GEMM commute: both row-linear)
// ---------------------------------------------------------------------------

#define NMAX 100096
#define EMAX 1600000
#define DD 128
#define CHUNKS 1024

__device__ float g_bufA[(size_t)NMAX * DD];   // agg buffer / 40-wide t buffer
__device__ float g_bufB[(size_t)NMAX * DD];   // gemm output / next layer input
__device__ float g_dout_is[NMAX];
__device__ float g_din_is[NMAX];
__device__ int   g_deg_out[NMAX];
__device__ int   g_deg_in[NMAX];
__device__ int   g_row_off[NMAX + 1];
__device__ int   g_cursor[NMAX];
__device__ int   g_csr_src[EMAX];
__device__ int   g_chunk_sum[CHUNKS];
__device__ float g_colsum[DD];  // zero-init; bn_finalize re-zeros after use
__device__ float g_colsq[DD];
__device__ float g_bn_a[DD];
__device__ float g_bn_b[DD];

// packed f32x2 helpers (sm_100+: lowers to FFMA2 / 64-bit regs)
#define FMA_F32X2(d, a, b, c) \
    asm("fma.rn.f32x2 %0, %1, %2, %3;" \
        : "=l"(d) : "l"(a), "l"(b), "l"(c))
#define PACKF2(out, lo, hi) \
    asm("mov.b64 %0, {%1, %2};" \
        : "=l"(out) : "r"(__float_as_uint(lo)), "r"(__float_as_uint(hi)))
#define UNPACKF2(lo, hi, in) \
    do { unsigned int _ulo, _uhi; \
         asm("mov.b64 {%0, %1}, %2;" : "=r"(_ulo), "=r"(_uhi) : "l"(in)); \
         lo = __uint_as_float(_ulo); hi = __uint_as_float(_uhi); } while (0)

// ---------------------------------------------------------------------------
__global__ void zero_deg_kernel(int n) {
    int i = blockIdx.x * blockDim.x + threadIdx.x;
    if (i < n) { g_deg_out[i] = 0; g_deg_in[i] = 0; }
}

__global__ void deg_count_kernel(const int* __restrict__ src,
                                 const int* __restrict__ dst, int E) {
    int i = blockIdx.x * blockDim.x + threadIdx.x;
    if (i < E) {
        atomicAdd(&g_deg_out[src[i]], 1);
        atomicAdd(&g_deg_in[dst[i]], 1);
    }
}

__global__ void deg_inv_kernel(int n) {
    int i = blockIdx.x * blockDim.x + threadIdx.x;
    if (i < n) {
        g_dout_is[i] = rsqrtf(fmaxf((float)g_deg_out[i], 1.f));
        g_din_is[i]  = rsqrtf(fmaxf((float)g_deg_in[i], 1.f));
    }
}

// ---------------------------------------------------------------------------
// Parallel exclusive scan of deg_in -> row_off (3 phases, full-chip).
// ---------------------------------------------------------------------------
__global__ void __launch_bounds__(256) chunk_sum_kernel(int N, int chunk) {
    int w = blockIdx.x * 8 + (threadIdx.x >> 5);
    if (w >= CHUNKS) return;
    int lane = threadIdx.x & 31;
    int lo = w * chunk, hi = min(lo + chunk, N);
    int s = 0;
    for (int i = lo + lane; i < hi; i += 32) s += g_deg_in[i];
    #pragma unroll
    for (int off = 16; off; off >>= 1)
        s += __shfl_down_sync(0xffffffffu, s, off);
    if (lane == 0) g_chunk_sum[w] = s;
}

__global__ void __launch_bounds__(1024) scan_chunks_kernel(int N) {
    __shared__ int sdata[1024];
    int t = threadIdx.x;
    int v = g_chunk_sum[t];
    sdata[t] = v;
    __syncthreads();
    #pragma unroll
    for (int off = 1; off < 1024; off <<= 1) {
        int u = (t >= off) ? sdata[t - off] : 0;
        __syncthreads();
        sdata[t] += u;
        __syncthreads();
    }
    g_chunk_sum[t] = sdata[t] - v;          // exclusive prefix per chunk
    if (t == 1023) g_row_off[N] = sdata[1023];
}

__global__ void __launch_bounds__(256) fill_off_kernel(int N, int chunk) {
    int w = blockIdx.x * 8 + (threadIdx.x >> 5);
    if (w >= CHUNKS) return;
    int lane = threadIdx.x & 31;
    int lo = w * chunk, hi = min(lo + chunk, N);
    int run = g_chunk_sum[w];
    for (int base = lo; base < hi; base += 32) {
        int i = base + lane;
        int v = (i < hi) ? __ldg(&g_deg_in[i]) : 0;
        int incl = v;
        #pragma unroll
        for (int off = 1; off < 32; off <<= 1) {
            int t = __shfl_up_sync(0xffffffffu, incl, off);
            if (lane >= off) incl += t;
        }
        if (i < hi) {
            int off_i = run + incl - v;
            g_row_off[i] = off_i;
            g_cursor[i]  = off_i;
        }
        run += __shfl_sync(0xffffffffu, incl, 31);
    }
}

__global__ void csr_fill_kernel(const int* __restrict__ src,
                                const int* __restrict__ dst, int E) {
    int i = blockIdx.x * blockDim.x + threadIdx.x;
    if (i < E) {
        int pos = atomicAdd(&g_cursor[dst[i]], 1);
        g_csr_src[pos] = src[i];
    }
}

// ---------------------------------------------------------------------------
// CSR propagation: one warp per dst node. Lane l owns features [4l, 4l+4).
// acc = sum over in-edges of (USE_BN ? relu(in*a+b) : in)[s] * dout_is[s].
// Inner loop unrolled x4: batch shfls, 4 independent LDG.128 in flight.
// ---------------------------------------------------------------------------
template <int USE_BN>
__global__ void __launch_bounds__(256) prop_csr_kernel(
    const float4* __restrict__ in, float* __restrict__ out, int N)
{
    int node = blockIdx.x * 8 + (threadIdx.x >> 5);
    if (node >= N) return;
    int lane = threadIdx.x & 31;
    int start = __ldg(&g_row_off[node]);
    int end   = __ldg(&g_row_off[node + 1]);

    float4 bnA, bnB;
    if (USE_BN) {
        bnA = __ldg(((const float4*)g_bn_a) + lane);
        bnB = __ldg(((const float4*)g_bn_b) + lane);
    }

    float4 acc = make_float4(0.f, 0.f, 0.f, 0.f);
    for (int base = start; base < end; base += 32) {
        int n = min(32, end - base);
        int s = 0; float sc = 0.f;
        if (lane < n) {
            s  = __ldg(g_csr_src + base + lane);
            sc = __ldg(&g_dout_is[s]);
        }
        int j = 0;
        for (; j + 4 <= n; j += 4) {
            int s0 = __shfl_sync(0xffffffffu, s, j);
            int s1 = __shfl_sync(0xffffffffu, s, j + 1);
            int s2 = __shfl_sync(0xffffffffu, s, j + 2);
            int s3 = __shfl_sync(0xffffffffu, s, j + 3);
            float c0 = __shfl_sync(0xffffffffu, sc, j);
            float c1 = __shfl_sync(0xffffffffu, sc, j + 1);
            float c2 = __shfl_sync(0xffffffffu, sc, j + 2);
            float c3 = __shfl_sync(0xffffffffu, sc, j + 3);
            float4 v0 = __ldg(in + (size_t)s0 * 32 + lane);
            float4 v1 = __ldg(in + (size_t)s1 * 32 + lane);
            float4 v2 = __ldg(in + (size_t)s2 * 32 + lane);
            float4 v3 = __ldg(in + (size_t)s3 * 32 + lane);
            if (USE_BN) {
                v0.x = fmaxf(fmaf(v0.x, bnA.x, bnB.x), 0.f);
                v0.y = fmaxf(fmaf(v0.y, bnA.y, bnB.y), 0.f);
                v0.z = fmaxf(fmaf(v0.z, bnA.z, bnB.z), 0.f);
                v0.w = fmaxf(fmaf(v0.w, bnA.w, bnB.w), 0.f);
                v1.x = fmaxf(fmaf(v1.x, bnA.x, bnB.x), 0.f);
                v1.y = fmaxf(fmaf(v1.y, bnA.y, bnB.y), 0.f);
                v1.z = fmaxf(fmaf(v1.z, bnA.z, bnB.z), 0.f);
                v1.w = fmaxf(fmaf(v1.w, bnA.w, bnB.w), 0.f);
                v2.x = fmaxf(fmaf(v2.x, bnA.x, bnB.x), 0.f);
                v2.y = fmaxf(fmaf(v2.y, bnA.y, bnB.y), 0.f);
                v2.z = fmaxf(fmaf(v2.z, bnA.z, bnB.z), 0.f);
                v2.w = fmaxf(fmaf(v2.w, bnA.w, bnB.w), 0.f);
                v3.x = fmaxf(fmaf(v3.x, bnA.x, bnB.x), 0.f);
                v3.y = fmaxf(fmaf(v3.y, bnA.y, bnB.y), 0.f);
                v3.z = fmaxf(fmaf(v3.z, bnA.z, bnB.z), 0.f);
                v3.w = fmaxf(fmaf(v3.w, bnA.w, bnB.w), 0.f);
            }
            acc.x = fmaf(v0.x, c0, acc.x); acc.y = fmaf(v0.y, c0, acc.y);
            acc.z = fmaf(v0.z, c0, acc.z); acc.w = fmaf(v0.w, c0, acc.w);
            acc.x = fmaf(v1.x, c1, acc.x); acc.y = fmaf(v1.y, c1, acc.y);
            acc.z = fmaf(v1.z, c1, acc.z); acc.w = fmaf(v1.w, c1, acc.w);
            acc.x = fmaf(v2.x, c2, acc.x); acc.y = fmaf(v2.y, c2, acc.y);
            acc.z = fmaf(v2.z, c2, acc.z); acc.w = fmaf(v2.w, c2, acc.w);
            acc.x = fmaf(v3.x, c3, acc.x); acc.y = fmaf(v3.y, c3, acc.y);
            acc.z = fmaf(v3.z, c3, acc.z); acc.w = fmaf(v3.w, c3, acc.w);
        }
        for (; j < n; j++) {
            int   sj  = __shfl_sync(0xffffffffu, s, j);
            float scj = __shfl_sync(0xffffffffu, sc, j);
            float4 v = __ldg(in + (size_t)sj * 32 + lane);
            if (USE_BN) {
                v.x = fmaxf(fmaf(v.x, bnA.x, bnB.x), 0.f);
                v.y = fmaxf(fmaf(v.y, bnA.y, bnB.y), 0.f);
                v.z = fmaxf(fmaf(v.z, bnA.z, bnB.z), 0.f);
                v.w = fmaxf(fmaf(v.w, bnA.w, bnB.w), 0.f);
            }
            acc.x = fmaf(v.x, scj, acc.x);
            acc.y = fmaf(v.y, scj, acc.y);
            acc.z = fmaf(v.z, scj, acc.z);
            acc.w = fmaf(v.w, scj, acc.w);
        }
    }
    ((float4*)out)[(size_t)node * 32 + lane] = acc;
}

// ---------------------------------------------------------------------------
// GEMM: out[r,c] = din_is[r] * (A[r,:] @ W[:,c]) + bias[c], D=128 square,
// with BN column stats (sum, sumsq of out) fused into the epilogue.
// Inner loop: packed fma.rn.f32x2 over row pairs.
// ---------------------------------------------------------------------------
#define SMEM128 ((128 * 128 + 128 * 68 + 256) * 4)

__global__ void __launch_bounds__(256) gemm128_kernel(
    const float* __restrict__ A, const float* __restrict__ W,
    const float* __restrict__ bias, float* __restrict__ out, int N)
{
    extern __shared__ float sm[];
    float* sW   = sm;                        // [k][c], 128*128
    float* sAT  = sm + 128 * 128;            // [k][r], leading dim 68
    float* sSum = sAT + 128 * 68;            // [128]
    float* sSq  = sSum + 128;                // [128]
    int tid  = threadIdx.x;
    int row0 = blockIdx.x * 64;

    if (tid < 128) { sSum[tid] = 0.f; sSq[tid] = 0.f; }

    {
        const float4* W4 = (const float4*)W;
        float4* sW4 = (float4*)sW;
        #pragma unroll
        for (int i = 0; i < 16; i++) sW4[tid + i * 256] = __ldg(W4 + tid + i * 256);
    }
    #pragma unroll
    for (int ii = 0; ii < 8; ii++) {
        int i  = tid + ii * 256;           // 2048 float4 total
        int r  = i >> 5;
        int k4 = (i & 31) << 2;
        int rr = row0 + r;
        float4 v = make_float4(0.f, 0.f, 0.f, 0.f);
        if (rr < N) v = __ldg((const float4*)(A + (size_t)rr * 128 + k4));
        sAT[(k4 + 0) * 68 + r] = v.x;
        sAT[(k4 + 1) * 68 + r] = v.y;
        sAT[(k4 + 2) * 68 + r] = v.z;
        sAT[(k4 + 3) * 68 + r] = v.w;
    }
    __syncthreads();

    int cg = (tid & 31) << 2;   // cols [cg, cg+4)
    int rg = (tid >> 5) << 3;   // rows [rg, rg+8)

    unsigned long long accp[4][4];
    #pragma unroll
    for (int pr = 0; pr < 4; pr++)
        #pragma unroll
        for (int j = 0; j < 4; j++) accp[pr][j] = 0ull;

    #pragma unroll 8
    for (int k = 0; k < 128; k++) {
        float4 wv = *(const float4*)(sW + k * 128 + cg);
        const ulonglong2* apt = (const ulonglong2*)(sAT + k * 68 + rg);
        ulonglong2 a01 = apt[0];
        ulonglong2 a23 = apt[1];
        unsigned long long ap[4] = {a01.x, a01.y, a23.x, a23.y};
        unsigned long long wd[4];
        PACKF2(wd[0], wv.x, wv.x);
        PACKF2(wd[1], wv.y, wv.y);
        PACKF2(wd[2], wv.z, wv.z);
        PACKF2(wd[3], wv.w, wv.w);
        #pragma unroll
        for (int pr = 0; pr < 4; pr++)
            #pragma unroll
            for (int j = 0; j < 4; j++)
                FMA_F32X2(accp[pr][j], ap[pr], wd[j], accp[pr][j]);
    }

    float acc[8][4];
    #pragma unroll
    for (int pr = 0; pr < 4; pr++)
        #pragma unroll
        for (int j = 0; j < 4; j++) {
            float lo, hi;
            UNPACKF2(lo, hi, accp[pr][j]);
            acc[2 * pr + 0][j] = lo;
            acc[2 * pr + 1][j] = hi;
        }

    float4 bv = __ldg((const float4*)(bias + cg));
    float csum[4] = {0.f, 0.f, 0.f, 0.f};
    float csq[4]  = {0.f, 0.f, 0.f, 0.f};
    #pragma unroll
    for (int i = 0; i < 8; i++) {
        int rr = row0 + rg + i;
        if (rr < N) {
            float sc = __ldg(&g_din_is[rr]);
            float4 o;
            o.x = fmaf(acc[i][0], sc, bv.x);
            o.y = fmaf(acc[i][1], sc, bv.y);
            o.z = fmaf(acc[i][2], sc, bv.z);
            o.w = fmaf(acc[i][3], sc, bv.w);
            csum[0] += o.x; csq[0] = fmaf(o.x, o.x, csq[0]);
            csum[1] += o.y; csq[1] = fmaf(o.y, o.y, csq[1]);
            csum[2] += o.z; csq[2] = fmaf(o.z, o.z, csq[2]);
            csum[3] += o.w; csq[3] = fmaf(o.w, o.w, csq[3]);
            *(float4*)(out + (size_t)rr * 128 + cg) = o;
        }
    }
    #pragma unroll
    for (int j = 0; j < 4; j++) {
        atomicAdd(&sSum[cg + j], csum[j]);
        atomicAdd(&sSq[cg + j],  csq[j]);
    }
    __syncthreads();
    if (tid < 128) {
        atomicAdd(&g_colsum[tid], sSum[tid]);
        atomicAdd(&g_colsq[tid],  sSq[tid]);
    }
}

__global__ void bn_finalize_kernel(const float* __restrict__ g,
                                   const float* __restrict__ be, float invN) {
    int c = threadIdx.x;  // 128 threads
    float mu  = g_colsum[c] * invN;
    float var = fmaf(-mu, mu, g_colsq[c] * invN);
    float a   = __ldg(g + c) * rsqrtf(var + 1e-5f);
    g_bn_a[c] = a;
    g_bn_b[c] = fmaf(-mu, a, __ldg(be + c));
    g_colsum[c] = 0.f;  // reset for next BN / next launch
    g_colsq[c]  = 0.f;
}

// ---------------------------------------------------------------------------
// Layer-3 pre-prop GEMM: t[r, 0..39] = dout_is[r] * (relu(bn(A[r,:])) @ W3).
// BN+ReLU applied while staging A into shared (per-feature k coefficients).
// Block: 64 rows. W3 zero-padded to 128x64 in shared. 4x4 per thread.
// t rows are 40 floats, stride 40 (160B, 32B-aligned).
// ---------------------------------------------------------------------------
#define SMEM40 ((128 * 64 + 128 * 68) * 4)

__global__ void __launch_bounds__(256) gemm40pre_kernel(
    const float* __restrict__ A, const float* __restrict__ W3,
    float* __restrict__ t, int N)
{
    extern __shared__ float sm[];
    float* sW   = sm;                       // [k][c] padded to 64 cols
    float* sAT  = sm + 128 * 64;            // [k][r] ld 68
    int tid  = threadIdx.x;
    int row0 = blockIdx.x * 64;

    for (int i = tid; i < 128 * 64; i += 256) sW[i] = 0.f;
    __syncthreads();
    for (int i = tid; i < 128 * 40; i += 256) {
        int k = i / 40, c = i - k * 40;
        sW[k * 64 + c] = __ldg(W3 + i);
    }
    #pragma unroll
    for (int ii = 0; ii < 8; ii++) {
        int i  = tid + ii * 256;
        int r  = i >> 5;
        int k4 = (i & 31) << 2;
        int rr = row0 + r;
        float4 v = make_float4(0.f, 0.f, 0.f, 0.f);
        if (rr < N) v = __ldg((const float4*)(A + (size_t)rr * 128 + k4));
        float4 a = __ldg(((const float4*)g_bn_a) + (k4 >> 2));
        float4 b = __ldg(((const float4*)g_bn_b) + (k4 >> 2));
        sAT[(k4 + 0) * 68 + r] = fmaxf(fmaf(v.x, a.x, b.x), 0.f);
        sAT[(k4 + 1) * 68 + r] = fmaxf(fmaf(v.y, a.y, b.y), 0.f);
        sAT[(k4 + 2) * 68 + r] = fmaxf(fmaf(v.z, a.z, b.z), 0.f);
        sAT[(k4 + 3) * 68 + r] = fmaxf(fmaf(v.w, a.w, b.w), 0.f);
    }
    __syncthreads();

    int cg = (tid & 15) << 2;   // cols [cg, cg+4) of 64 (only <40 real)
    int rg = (tid >> 4) << 2;   // rows [rg, rg+4)
    float acc[4][4];
    #pragma unroll
    for (int i = 0; i < 4; i++)
        #pragma unroll
        for (int j = 0; j < 4; j++) acc[i][j] = 0.f;

    #pragma unroll 8
    for (int k = 0; k < 128; k++) {
        float4 wv = *(const float4*)(sW + k * 64 + cg);
        float4 av = *(const float4*)(sAT + k * 68 + rg);
        float ar[4] = {av.x, av.y, av.z, av.w};
        #pragma unroll
        for (int i = 0; i < 4; i++) {
            acc[i][0] = fmaf(ar[i], wv.x, acc[i][0]);
            acc[i][1] = fmaf(ar[i], wv.y, acc[i][1]);
            acc[i][2] = fmaf(ar[i], wv.z, acc[i][2]);
            acc[i][3] = fmaf(ar[i], wv.w, acc[i][3]);
        }
    }

    if (cg < 40) {
        #pragma unroll
        for (int i = 0; i < 4; i++) {
            int rr = row0 + rg + i;
            if (rr < N) {
                float sc = __ldg(&g_dout_is[rr]);
                float4 o;
                o.x = acc[i][0] * sc;
                o.y = acc[i][1] * sc;
                o.z = acc[i][2] * sc;
                o.w = acc[i][3] * sc;
                *(float4*)(t + (size_t)rr * 40 + cg) = o;
            }
        }
    }
}

// ---------------------------------------------------------------------------
// 40-wide CSR propagation + bias + log_softmax. One warp per dst node.
// Lanes 0..9 each own 4 of the 40 features (float4). All 32 lanes stage the
// CSR indices. MLP-4 pipelined gathers. Softmax reduced via 32-lane butterfly
// (idle lanes contribute -inf / 0).
// ---------------------------------------------------------------------------
__global__ void __launch_bounds__(256) prop40_kernel(
    const float* __restrict__ t, const float* __restrict__ b3,
    float* __restrict__ out, int N)
{
    int node = blockIdx.x * 8 + (threadIdx.x >> 5);
    if (node >= N) return;
    int lane = threadIdx.x & 31;
    bool act = lane < 10;
    int start = __ldg(&g_row_off[node]);
    int end   = __ldg(&g_row_off[node + 1]);

    float4 acc = make_float4(0.f, 0.f, 0.f, 0.f);
    for (int base = start; base < end; base += 32) {
        int n = min(32, end - base);
        int s = 0;
        if (lane < n) s = __ldg(g_csr_src + base + lane);
        int j = 0;
        for (; j + 4 <= n; j += 4) {
            int s0 = __shfl_sync(0xffffffffu, s, j);
            int s1 = __shfl_sync(0xffffffffu, s, j + 1);
            int s2 = __shfl_sync(0xffffffffu, s, j + 2);
            int s3 = __shfl_sync(0xffffffffu, s, j + 3);
            if (act) {
                float4 v0 = __ldg((const float4*)(t + (size_t)s0 * 40) + lane);
                float4 v1 = __ldg((const float4*)(t + (size_t)s1 * 40) + lane);
                float4 v2 = __ldg((const float4*)(t + (size_t)s2 * 40) + lane);
                float4 v3 = __ldg((const float4*)(t + (size_t)s3 * 40) + lane);
                acc.x += v0.x + v1.x + v2.x + v3.x;
                acc.y += v0.y + v1.y + v2.y + v3.y;
                acc.z += v0.z + v1.z + v2.z + v3.z;
                acc.w += v0.w + v1.w + v2.w + v3.w;
            }
        }
        for (; j < n; j++) {
            int sj = __shfl_sync(0xffffffffu, s, j);
            if (act) {
                float4 v = __ldg((const float4*)(t + (size_t)sj * 40) + lane);
                acc.x += v.x; acc.y += v.y; acc.z += v.z; acc.w += v.w;
            }
        }
    }

    float din = __ldg(&g_din_is[node]);
    float4 o = make_float4(0.f, 0.f, 0.f, 0.f);
    if (act) {
        float4 bv = __ldg(((const float4*)b3) + lane);
        o.x = fmaf(acc.x, din, bv.x);
        o.y = fmaf(acc.y, din, bv.y);
        o.z = fmaf(acc.z, din, bv.z);
        o.w = fmaf(acc.w, din, bv.w);
    }
    float m = act ? fmaxf(fmaxf(o.x, o.y), fmaxf(o.z, o.w)) : -1e30f;
    #pragma unroll
    for (int off = 16; off; off >>= 1)
        m = fmaxf(m, __shfl_xor_sync(0xffffffffu, m, off));
    float e = act ? (expf(o.x - m) + expf(o.y - m) +
                     expf(o.z - m) + expf(o.w - m)) : 0.f;
    #pragma unroll
    for (int off = 16; off; off >>= 1)
        e += __shfl_xor_sync(0xffffffffu, e, off);
    float lse = m + logf(e);
    if (act) {
        float4 r;
        r.x = o.x - lse; r.y = o.y - lse; r.z = o.z - lse; r.w = o.w - lse;
        *(float4*)(out + (size_t)node * 40 + lane * 4) = r;
    }
}

// ---------------------------------------------------------------------------
extern "C" void kernel_launch(void* const* d_in, const int* in_sizes, int n_in,
                              void* d_out, int out_size)
{
    const float* x   = (const float*)d_in[0];
    const int*   src = (const int*)d_in[1];
    const int*   dst = (const int*)d_in[2];
    const float* W1  = (const float*)d_in[3];
    const float* b1  = (const float*)d_in[4];
    const float* g1  = (const float*)d_in[5];
    const float* be1 = (const float*)d_in[6];
    const float* W2  = (const float*)d_in[7];
    const float* b2  = (const float*)d_in[8];
    const float* g2  = (const float*)d_in[9];
    const float* be2 = (const float*)d_in[10];
    const float* W3  = (const float*)d_in[11];
    const float* b3  = (const float*)d_in[12];

    int N = in_sizes[0] / DD;
    int E = in_sizes[1];
    float* out = (float*)d_out;

    float *bufA, *bufB;
    cudaGetSymbolAddress((void**)&bufA, g_bufA);
    cudaGetSymbolAddress((void**)&bufB, g_bufB);

    cudaFuncSetAttribute(gemm128_kernel,
                         cudaFuncAttributeMaxDynamicSharedMemorySize, SMEM128);
    cudaFuncSetAttribute(gemm40pre_kernel,
                         cudaFuncAttributeMaxDynamicSharedMemorySize, SMEM40);

    int ngrid  = (N + 255) / 256;
    int egrid  = (E + 255) / 256;
    int pgrid  = (N + 7) / 8;      // 8 warps (nodes) per 256-thread block
    int ggrid  = (N + 63) / 64;
    int chunk  = (N + CHUNKS - 1) / CHUNKS;
    float invN = 1.0f / (float)N;

    // degrees + CSR-by-dst
    zero_deg_kernel<<<ngrid, 256>>>(N);
    deg_count_kernel<<<egrid, 256>>>(src, dst, E);
    deg_inv_kernel<<<ngrid, 256>>>(N);
    chunk_sum_kernel<<<CHUNKS / 8, 256>>>(N, chunk);
    scan_chunks_kernel<<<1, 1024>>>(N);
    fill_off_kernel<<<CHUNKS / 8, 256>>>(N, chunk);
    csr_fill_kernel<<<egrid, 256>>>(src, dst, E);

    // layer 1
    prop_csr_kernel<0><<<pgrid, 256>>>((const float4*)x, bufA, N);
    gemm128_kernel<<<ggrid, 256, SMEM128>>>(bufA, W1, b1, bufB, N);
    bn_finalize_kernel<<<1, 128>>>(g1, be1, invN);

    // layer 2
    prop_csr_kernel<1><<<pgrid, 256>>>((const float4*)bufB, bufA, N);
    gemm128_kernel<<<ggrid, 256, SMEM128>>>(bufA, W2, b2, bufB, N);
    bn_finalize_kernel<<<1, 128>>>(g2, be2, invN);

    // layer 3: GEMM first (prop and @W3 commute), then 40-wide prop
    //          with fused bias + log_softmax
    gemm40pre_kernel<<<ggrid, 256, SMEM40>>>(bufB, W3, bufA, N);
    prop40_kernel<<<pgrid, 256>>>(bufA, b3, out, N);
}

// round 8
// speedup vs baseline: 2.0427x; 1.1138x over previous
#include <cuda_runtime.h>
#include <cuda_fp16.h>

// ---------------------------------------------------------------------------
// GCN: 3x (GraphConv norm='both') with BN+ReLU between, log_softmax at end.
// N=100000 nodes, E=1.6M edges, D=128, C=40.
//
// Round-8 pipeline (graph-capturable, alloc-free):
//   degrees (int atomics) -> deg^-1/2
//   CSR-by-dst build: parallel 3-phase scan + atomic-cursor fill
//   L1: prep (x * dout -> fp16 rows); prop_fp16 (warp/node, fp32 accum);
//       gemm128 (f32x2, fused BN stats); bn_finalize
//   L2: prep with BN+ReLU; prop_fp16; gemm128 (fused stats); bn_finalize
//   L3: gemm40pre (BN+ReLU on load, @W3, dout scale, f32x2) ->
//       40-wide fp32 prop with fused bias + log_softmax
// ---------------------------------------------------------------------------

#define NMAX 100096
#define EMAX 1600000
#define DD 128
#define CHUNKS 1024

__device__ float   g_bufA[(size_t)NMAX * DD];   // agg buffer / 40-wide t buffer
__device__ float   g_bufB[(size_t)NMAX * DD];   // gemm output / next layer input
__device__ __half2 g_half[(size_t)NMAX * 64];   // fp16 gather copy (256B/row)
__device__ float   g_dout_is[NMAX];
__device__ float   g_din_is[NMAX];
__device__ int     g_deg_out[NMAX];
__device__ int     g_deg_in[NMAX];
__device__ int     g_row_off[NMAX + 1];
__device__ int     g_cursor[NMAX];
__device__ int     g_csr_src[EMAX];
__device__ int     g_chunk_sum[CHUNKS];
__device__ float   g_colsum[DD];  // zero-init; bn_finalize re-zeros after use
__device__ float   g_colsq[DD];
__device__ float   g_bn_a[DD];
__device__ float   g_bn_b[DD];

// packed f32x2 helpers (sm_100+: lowers to FFMA2 / 64-bit regs)
#define FMA_F32X2(d, a, b, c) \
    asm("fma.rn.f32x2 %0, %1, %2, %3;" \
        : "=l"(d) : "l"(a), "l"(b), "l"(c))
#define PACKF2(out, lo, hi) \
    asm("mov.b64 %0, {%1, %2};" \
        : "=l"(out) : "r"(__float_as_uint(lo)), "r"(__float_as_uint(hi)))
#define UNPACKF2(lo, hi, in) \
    do { unsigned int _ulo, _uhi; \
         asm("mov.b64 {%0, %1}, %2;" : "=r"(_ulo), "=r"(_uhi) : "l"(in)); \
         lo = __uint_as_float(_ulo); hi = __uint_as_float(_uhi); } while (0)

// ---------------------------------------------------------------------------
__global__ void zero_deg_kernel(int n) {
    int i = blockIdx.x * blockDim.x + threadIdx.x;
    if (i < n) { g_deg_out[i] = 0; g_deg_in[i] = 0; }
}

__global__ void deg_count_kernel(const int* __restrict__ src,
                                 const int* __restrict__ dst, int E) {
    int i = blockIdx.x * blockDim.x + threadIdx.x;
    if (i < E) {
        atomicAdd(&g_deg_out[src[i]], 1);
        atomicAdd(&g_deg_in[dst[i]], 1);
    }
}

__global__ void deg_inv_kernel(int n) {
    int i = blockIdx.x * blockDim.x + threadIdx.x;
    if (i < n) {
        g_dout_is[i] = rsqrtf(fmaxf((float)g_deg_out[i], 1.f));
        g_din_is[i]  = rsqrtf(fmaxf((float)g_deg_in[i], 1.f));
    }
}

// ---------------------------------------------------------------------------
// Parallel exclusive scan of deg_in -> row_off (3 phases, full-chip).
// ---------------------------------------------------------------------------
__global__ void __launch_bounds__(256) chunk_sum_kernel(int N, int chunk) {
    int w = blockIdx.x * 8 + (threadIdx.x >> 5);
    if (w >= CHUNKS) return;
    int lane = threadIdx.x & 31;
    int lo = w * chunk, hi = min(lo + chunk, N);
    int s = 0;
    for (int i = lo + lane; i < hi; i += 32) s += g_deg_in[i];
    #pragma unroll
    for (int off = 16; off; off >>= 1)
        s += __shfl_down_sync(0xffffffffu, s, off);
    if (lane == 0) g_chunk_sum[w] = s;
}

__global__ void __launch_bounds__(1024) scan_chunks_kernel(int N) {
    __shared__ int sdata[1024];
    int t = threadIdx.x;
    int v = g_chunk_sum[t];
    sdata[t] = v;
    __syncthreads();
    #pragma unroll
    for (int off = 1; off < 1024; off <<= 1) {
        int u = (t >= off) ? sdata[t - off] : 0;
        __syncthreads();
        sdata[t] += u;
        __syncthreads();
    }
    g_chunk_sum[t] = sdata[t] - v;          // exclusive prefix per chunk
    if (t == 1023) g_row_off[N] = sdata[1023];
}

__global__ void __launch_bounds__(256) fill_off_kernel(int N, int chunk) {
    int w = blockIdx.x * 8 + (threadIdx.x >> 5);
    if (w >= CHUNKS) return;
    int lane = threadIdx.x & 31;
    int lo = w * chunk, hi = min(lo + chunk, N);
    int run = g_chunk_sum[w];
    for (int base = lo; base < hi; base += 32) {
        int i = base + lane;
        int v = (i < hi) ? __ldg(&g_deg_in[i]) : 0;
        int incl = v;
        #pragma unroll
        for (int off = 1; off < 32; off <<= 1) {
            int t = __shfl_up_sync(0xffffffffu, incl, off);
            if (lane >= off) incl += t;
        }
        if (i < hi) {
            int off_i = run + incl - v;
            g_row_off[i] = off_i;
            g_cursor[i]  = off_i;
        }
        run += __shfl_sync(0xffffffffu, incl, 31);
    }
}

__global__ void csr_fill_kernel(const int* __restrict__ src,
                                const int* __restrict__ dst, int E) {
    int i = blockIdx.x * blockDim.x + threadIdx.x;
    if (i < E) {
        int pos = atomicAdd(&g_cursor[dst[i]], 1);
        g_csr_src[pos] = src[i];
    }
}

// ---------------------------------------------------------------------------
// Prep: per-node (not per-edge!) BN+ReLU + dout scaling, emit fp16 rows.
// One thread per float4 (4 features). Coalesced read + write.
// ---------------------------------------------------------------------------
template <int USE_BN>
__global__ void __launch_bounds__(256) prep_kernel(
    const float4* __restrict__ in, __half2* __restrict__ outh, int N)
{
    int i = blockIdx.x * blockDim.x + threadIdx.x;
    if (i >= N * 32) return;
    int node = i >> 5;
    int q    = i & 31;
    float4 v = __ldg(in + i);
    if (USE_BN) {
        float4 a = __ldg(((const float4*)g_bn_a) + q);
        float4 b = __ldg(((const float4*)g_bn_b) + q);
        v.x = fmaxf(fmaf(v.x, a.x, b.x), 0.f);
        v.y = fmaxf(fmaf(v.y, a.y, b.y), 0.f);
        v.z = fmaxf(fmaf(v.z, a.z, b.z), 0.f);
        v.w = fmaxf(fmaf(v.w, a.w, b.w), 0.f);
    }
    float sc = __ldg(&g_dout_is[node]);
    outh[i * 2 + 0] = __floats2half2_rn(v.x * sc, v.y * sc);
    outh[i * 2 + 1] = __floats2half2_rn(v.z * sc, v.w * sc);
}

// ---------------------------------------------------------------------------
// fp16 CSR propagation: one warp per dst node. Lane l owns features
// [4l, 4l+4) as one uint2 (2x half2, 8B). Pure sum, fp32 accumulation.
// Inner loop unrolled x4: 4 independent LDG.64 in flight.
// ---------------------------------------------------------------------------
__global__ void __launch_bounds__(256) prop_fp16_kernel(
    const uint2* __restrict__ inh, float* __restrict__ out, int N)
{
    int node = blockIdx.x * 8 + (threadIdx.x >> 5);
    if (node >= N) return;
    int lane = threadIdx.x & 31;
    int start = __ldg(&g_row_off[node]);
    int end   = __ldg(&g_row_off[node + 1]);

    float4 acc = make_float4(0.f, 0.f, 0.f, 0.f);
    for (int base = start; base < end; base += 32) {
        int n = min(32, end - base);
        int s = 0;
        if (lane < n) s = __ldg(g_csr_src + base + lane);
        int j = 0;
        for (; j + 4 <= n; j += 4) {
            int s0 = __shfl_sync(0xffffffffu, s, j);
            int s1 = __shfl_sync(0xffffffffu, s, j + 1);
            int s2 = __shfl_sync(0xffffffffu, s, j + 2);
            int s3 = __shfl_sync(0xffffffffu, s, j + 3);
            uint2 r0 = __ldg(inh + (size_t)s0 * 32 + lane);
            uint2 r1 = __ldg(inh + (size_t)s1 * 32 + lane);
            uint2 r2 = __ldg(inh + (size_t)s2 * 32 + lane);
            uint2 r3 = __ldg(inh + (size_t)s3 * 32 + lane);
            float2 a0 = __half22float2(*(const __half2*)&r0.x);
            float2 b0 = __half22float2(*(const __half2*)&r0.y);
            float2 a1 = __half22float2(*(const __half2*)&r1.x);
            float2 b1 = __half22float2(*(const __half2*)&r1.y);
            float2 a2 = __half22float2(*(const __half2*)&r2.x);
            float2 b2 = __half22float2(*(const __half2*)&r2.y);
            float2 a3 = __half22float2(*(const __half2*)&r3.x);
            float2 b3 = __half22float2(*(const __half2*)&r3.y);
            acc.x += (a0.x + a1.x) + (a2.x + a3.x);
            acc.y += (a0.y + a1.y) + (a2.y + a3.y);
            acc.z += (b0.x + b1.x) + (b2.x + b3.x);
            acc.w += (b0.y + b1.y) + (b2.y + b3.y);
        }
        for (; j < n; j++) {
            int sj = __shfl_sync(0xffffffffu, s, j);
            uint2 r = __ldg(inh + (size_t)sj * 32 + lane);
            float2 a = __half22float2(*(const __half2*)&r.x);
            float2 b = __half22float2(*(const __half2*)&r.y);
            acc.x += a.x; acc.y += a.y; acc.z += b.x; acc.w += b.y;
        }
    }
    ((float4*)out)[(size_t)node * 32 + lane] = acc;
}

// ---------------------------------------------------------------------------
// GEMM: out[r,c] = din_is[r] * (A[r,:] @ W[:,c]) + bias[c], D=128 square,
// with BN column stats (sum, sumsq of out) fused into the epilogue.
// Inner loop: packed fma.rn.f32x2 over row pairs.
// ---------------------------------------------------------------------------
#define SMEM128 ((128 * 128 + 128 * 68 + 256) * 4)

__global__ void __launch_bounds__(256) gemm128_kernel(
    const float* __restrict__ A, const float* __restrict__ W,
    const float* __restrict__ bias, float* __restrict__ out, int N)
{
    extern __shared__ float sm[];
    float* sW   = sm;                        // [k][c], 128*128
    float* sAT  = sm + 128 * 128;            // [k][r], leading dim 68
    float* sSum = sAT + 128 * 68;            // [128]
    float* sSq  = sSum + 128;                // [128]
    int tid  = threadIdx.x;
    int row0 = blockIdx.x * 64;

    if (tid < 128) { sSum[tid] = 0.f; sSq[tid] = 0.f; }

    {
        const float4* W4 = (const float4*)W;
        float4* sW4 = (float4*)sW;
        #pragma unroll
        for (int i = 0; i < 16; i++) sW4[tid + i * 256] = __ldg(W4 + tid + i * 256);
    }
    #pragma unroll
    for (int ii = 0; ii < 8; ii++) {
        int i  = tid + ii * 256;           // 2048 float4 total
        int r  = i >> 5;
        int k4 = (i & 31) << 2;
        int rr = row0 + r;
        float4 v = make_float4(0.f, 0.f, 0.f, 0.f);
        if (rr < N) v = __ldg((const float4*)(A + (size_t)rr * 128 + k4));
        sAT[(k4 + 0) * 68 + r] = v.x;
        sAT[(k4 + 1) * 68 + r] = v.y;
        sAT[(k4 + 2) * 68 + r] = v.z;
        sAT[(k4 + 3) * 68 + r] = v.w;
    }
    __syncthreads();

    int cg = (tid & 31) << 2;   // cols [cg, cg+4)
    int rg = (tid >> 5) << 3;   // rows [rg, rg+8)

    unsigned long long accp[4][4];
    #pragma unroll
    for (int pr = 0; pr < 4; pr++)
        #pragma unroll
        for (int j = 0; j < 4; j++) accp[pr][j] = 0ull;

    #pragma unroll 8
    for (int k = 0; k < 128; k++) {
        float4 wv = *(const float4*)(sW + k * 128 + cg);
        const ulonglong2* apt = (const ulonglong2*)(sAT + k * 68 + rg);
        ulonglong2 a01 = apt[0];
        ulonglong2 a23 = apt[1];
        unsigned long long ap[4] = {a01.x, a01.y, a23.x, a23.y};
        unsigned long long wd[4];
        PACKF2(wd[0], wv.x, wv.x);
        PACKF2(wd[1], wv.y, wv.y);
        PACKF2(wd[2], wv.z, wv.z);
        PACKF2(wd[3], wv.w, wv.w);
        #pragma unroll
        for (int pr = 0; pr < 4; pr++)
            #pragma unroll
            for (int j = 0; j < 4; j++)
                FMA_F32X2(accp[pr][j], ap[pr], wd[j], accp[pr][j]);
    }

    float acc[8][4];
    #pragma unroll
    for (int pr = 0; pr < 4; pr++)
        #pragma unroll
        for (int j = 0; j < 4; j++) {
            float lo, hi;
            UNPACKF2(lo, hi, accp[pr][j]);
            acc[2 * pr + 0][j] = lo;
            acc[2 * pr + 1][j] = hi;
        }

    float4 bv = __ldg((const float4*)(bias + cg));
    float csum[4] = {0.f, 0.f, 0.f, 0.f};
    float csq[4]  = {0.f, 0.f, 0.f, 0.f};
    #pragma unroll
    for (int i = 0; i < 8; i++) {
        int rr = row0 + rg + i;
        if (rr < N) {
            float sc = __ldg(&g_din_is[rr]);
            float4 o;
            o.x = fmaf(acc[i][0], sc, bv.x);
            o.y = fmaf(acc[i][1], sc, bv.y);
            o.z = fmaf(acc[i][2], sc, bv.z);
            o.w = fmaf(acc[i][3], sc, bv.w);
            csum[0] += o.x; csq[0] = fmaf(o.x, o.x, csq[0]);
            csum[1] += o.y; csq[1] = fmaf(o.y, o.y, csq[1]);
            csum[2] += o.z; csq[2] = fmaf(o.z, o.z, csq[2]);
            csum[3] += o.w; csq[3] = fmaf(o.w, o.w, csq[3]);
            *(float4*)(out + (size_t)rr * 128 + cg) = o;
        }
    }
    #pragma unroll
    for (int j = 0; j < 4; j++) {
        atomicAdd(&sSum[cg + j], csum[j]);
        atomicAdd(&sSq[cg + j],  csq[j]);
    }
    __syncthreads();
    if (tid < 128) {
        atomicAdd(&g_colsum[tid], sSum[tid]);
        atomicAdd(&g_colsq[tid],  sSq[tid]);
    }
}

__global__ void bn_finalize_kernel(const float* __restrict__ g,
                                   const float* __restrict__ be, float invN) {
    int c = threadIdx.x;  // 128 threads
    float mu  = g_colsum[c] * invN;
    float var = fmaf(-mu, mu, g_colsq[c] * invN);
    float a   = __ldg(g + c) * rsqrtf(var + 1e-5f);
    g_bn_a[c] = a;
    g_bn_b[c] = fmaf(-mu, a, __ldg(be + c));
    g_colsum[c] = 0.f;  // reset for next BN / next launch
    g_colsq[c]  = 0.f;
}

// ---------------------------------------------------------------------------
// Layer-3 pre-prop GEMM: t[r, 0..39] = dout_is[r] * (relu(bn(A[r,:])) @ W3).
// BN+ReLU applied while staging A. f32x2 packed FMA over row pairs.
// ---------------------------------------------------------------------------
#define SMEM40 ((128 * 64 + 128 * 68) * 4)

__global__ void __launch_bounds__(256) gemm40pre_kernel(
    const float* __restrict__ A, const float* __restrict__ W3,
    float* __restrict__ t, int N)
{
    extern __shared__ float sm[];
    float* sW   = sm;                       // [k][c] padded to 64 cols
    float* sAT  = sm + 128 * 64;            // [k][r] ld 68
    int tid  = threadIdx.x;
    int row0 = blockIdx.x * 64;

    for (int i = tid; i < 128 * 64; i += 256) sW[i] = 0.f;
    __syncthreads();
    for (int i = tid; i < 128 * 40; i += 256) {
        int k = i / 40, c = i - k * 40;
        sW[k * 64 + c] = __ldg(W3 + i);
    }
    #pragma unroll
    for (int ii = 0; ii < 8; ii++) {
        int i  = tid + ii * 256;
        int r  = i >> 5;
        int k4 = (i & 31) << 2;
        int rr = row0 + r;
        float4 v = make_float4(0.f, 0.f, 0.f, 0.f);
        if (rr < N) v = __ldg((const float4*)(A + (size_t)rr * 128 + k4));
        float4 a = __ldg(((const float4*)g_bn_a) + (k4 >> 2));
        float4 b = __ldg(((const float4*)g_bn_b) + (k4 >> 2));
        sAT[(k4 + 0) * 68 + r] = fmaxf(fmaf(v.x, a.x, b.x), 0.f);
        sAT[(k4 + 1) * 68 + r] = fmaxf(fmaf(v.y, a.y, b.y), 0.f);
        sAT[(k4 + 2) * 68 + r] = fmaxf(fmaf(v.z, a.z, b.z), 0.f);
        sAT[(k4 + 3) * 68 + r] = fmaxf(fmaf(v.w, a.w, b.w), 0.f);
    }
    __syncthreads();

    int cg = (tid & 15) << 2;   // cols [cg, cg+4) of 64 (only <40 real)
    int rg = (tid >> 4) << 2;   // rows [rg, rg+4)

    unsigned long long accp[2][4];   // row pairs (rg,rg+1),(rg+2,rg+3)
    #pragma unroll
    for (int pr = 0; pr < 2; pr++)
        #pragma unroll
        for (int j = 0; j < 4; j++) accp[pr][j] = 0ull;

    #pragma unroll 8
    for (int k = 0; k < 128; k++) {
        float4 wv = *(const float4*)(sW + k * 64 + cg);
        ulonglong2 a01 = *(const ulonglong2*)(sAT + k * 68 + rg);
        unsigned long long ap[2] = {a01.x, a01.y};
        unsigned long long wd[4];
        PACKF2(wd[0], wv.x, wv.x);
        PACKF2(wd[1], wv.y, wv.y);
        PACKF2(wd[2], wv.z, wv.z);
        PACKF2(wd[3], wv.w, wv.w);
        #pragma unroll
        for (int pr = 0; pr < 2; pr++)
            #pragma unroll
            for (int j = 0; j < 4; j++)
                FMA_F32X2(accp[pr][j], ap[pr], wd[j], accp[pr][j]);
    }

    float acc[4][4];
    #pragma unroll
    for (int pr = 0; pr < 2; pr++)
        #pragma unroll
        for (int j = 0; j < 4; j++) {
            float lo, hi;
            UNPACKF2(lo, hi, accp[pr][j]);
            acc[2 * pr + 0][j] = lo;
            acc[2 * pr + 1][j] = hi;
        }

    if (cg < 40) {
        #pragma unroll
        for (int i = 0; i < 4; i++) {
            int rr = row0 + rg + i;
            if (rr < N) {
                float sc = __ldg(&g_dout_is[rr]);
                float4 o;
                o.x = acc[i][0] * sc;
                o.y = acc[i][1] * sc;
                o.z = acc[i][2] * sc;
                o.w = acc[i][3] * sc;
                *(float4*)(t + (size_t)rr * 40 + cg) = o;
            }
        }
    }
}

// ---------------------------------------------------------------------------
// 40-wide CSR propagation + bias + log_softmax. One warp per dst node.
// Lanes 0..9 each own 4 of the 40 features (float4, fp32 for final precision).
// ---------------------------------------------------------------------------
__global__ void __launch_bounds__(256) prop40_kernel(
    const float* __restrict__ t, const float* __restrict__ b3,
    float* __restrict__ out, int N)
{
    int node = blockIdx.x * 8 + (threadIdx.x >> 5);
    if (node >= N) return;
    int lane = threadIdx.x & 31;
    bool act = lane < 10;
    int start = __ldg(&g_row_off[node]);
    int end   = __ldg(&g_row_off[node + 1]);

    float4 acc = make_float4(0.f, 0.f, 0.f, 0.f);
    for (int base = start; base < end; base += 32) {
        int n = min(32, end - base);
        int s = 0;
        if (lane < n) s = __ldg(g_csr_src + base + lane);
        int j = 0;
        for (; j + 4 <= n; j += 4) {
            int s0 = __shfl_sync(0xffffffffu, s, j);
            int s1 = __shfl_sync(0xffffffffu, s, j + 1);
            int s2 = __shfl_sync(0xffffffffu, s, j + 2);
            int s3 = __shfl_sync(0xffffffffu, s, j + 3);
            if (act) {
                float4 v0 = __ldg((const float4*)(t + (size_t)s0 * 40) + lane);
                float4 v1 = __ldg((const float4*)(t + (size_t)s1 * 40) + lane);
                float4 v2 = __ldg((const float4*)(t + (size_t)s2 * 40) + lane);
                float4 v3 = __ldg((const float4*)(t + (size_t)s3 * 40) + lane);
                acc.x += v0.x + v1.x + v2.x + v3.x;
                acc.y += v0.y + v1.y + v2.y + v3.y;
                acc.z += v0.z + v1.z + v2.z + v3.z;
                acc.w += v0.w + v1.w + v2.w + v3.w;
            }
        }
        for (; j < n; j++) {
            int sj = __shfl_sync(0xffffffffu, s, j);
            if (act) {
                float4 v = __ldg((const float4*)(t + (size_t)sj * 40) + lane);
                acc.x += v.x; acc.y += v.y; acc.z += v.z; acc.w += v.w;
            }
        }
    }

    float din = __ldg(&g_din_is[node]);
    float4 o = make_float4(0.f, 0.f, 0.f, 0.f);
    if (act) {
        float4 bv = __ldg(((const float4*)b3) + lane);
        o.x = fmaf(acc.x, din, bv.x);
        o.y = fmaf(acc.y, din, bv.y);
        o.z = fmaf(acc.z, din, bv.z);
        o.w = fmaf(acc.w, din, bv.w);
    }
    float m = act ? fmaxf(fmaxf(o.x, o.y), fmaxf(o.z, o.w)) : -1e30f;
    #pragma unroll
    for (int off = 16; off; off >>= 1)
        m = fmaxf(m, __shfl_xor_sync(0xffffffffu, m, off));
    float e = act ? (expf(o.x - m) + expf(o.y - m) +
                     expf(o.z - m) + expf(o.w - m)) : 0.f;
    #pragma unroll
    for (int off = 16; off; off >>= 1)
        e += __shfl_xor_sync(0xffffffffu, e, off);
    float lse = m + logf(e);
    if (act) {
        float4 r;
        r.x = o.x - lse; r.y = o.y - lse; r.z = o.z - lse; r.w = o.w - lse;
        *(float4*)(out + (size_t)node * 40 + lane * 4) = r;
    }
}

// ---------------------------------------------------------------------------
extern "C" void kernel_launch(void* const* d_in, const int* in_sizes, int n_in,
                              void* d_out, int out_size)
{
    const float* x   = (const float*)d_in[0];
    const int*   src = (const int*)d_in[1];
    const int*   dst = (const int*)d_in[2];
    const float* W1  = (const float*)d_in[3];
    const float* b1  = (const float*)d_in[4];
    const float* g1  = (const float*)d_in[5];
    const float* be1 = (const float*)d_in[6];
    const float* W2  = (const float*)d_in[7];
    const float* b2  = (const float*)d_in[8];
    const float* g2  = (const float*)d_in[9];
    const float* be2 = (const float*)d_in[10];
    const float* W3  = (const float*)d_in[11];
    const float* b3  = (const float*)d_in[12];

    int N = in_sizes[0] / DD;
    int E = in_sizes[1];
    float* out = (float*)d_out;

    float *bufA, *bufB;
    __half2* bufH;
    cudaGetSymbolAddress((void**)&bufA, g_bufA);
    cudaGetSymbolAddress((void**)&bufB, g_bufB);
    cudaGetSymbolAddress((void**)&bufH, g_half);

    cudaFuncSetAttribute(gemm128_kernel,
                         cudaFuncAttributeMaxDynamicSharedMemorySize, SMEM128);
    cudaFuncSetAttribute(gemm40pre_kernel,
                         cudaFuncAttributeMaxDynamicSharedMemorySize, SMEM40);

    int ngrid  = (N + 255) / 256;
    int egrid  = (E + 255) / 256;
    int pgrid  = (N + 7) / 8;          // 8 warps (nodes) per 256-thread block
    int qgrid  = (N * 32 + 255) / 256; // prep: one thread per float4
    int ggrid  = (N + 63) / 64;
    int chunk  = (N + CHUNKS - 1) / CHUNKS;
    float invN = 1.0f / (float)N;

    // degrees + CSR-by-dst
    zero_deg_kernel<<<ngrid, 256>>>(N);
    deg_count_kernel<<<egrid, 256>>>(src, dst, E);
    deg_inv_kernel<<<ngrid, 256>>>(N);
    chunk_sum_kernel<<<CHUNKS / 8, 256>>>(N, chunk);
    scan_chunks_kernel<<<1, 1024>>>(N);
    fill_off_kernel<<<CHUNKS / 8, 256>>>(N, chunk);
    csr_fill_kernel<<<egrid, 256>>>(src, dst, E);

    // layer 1
    prep_kernel<0><<<qgrid, 256>>>((const float4*)x, bufH, N);
    prop_fp16_kernel<<<pgrid, 256>>>((const uint2*)bufH, bufA, N);
    gemm128_kernel<<<ggrid, 256, SMEM128>>>(bufA, W1, b1, bufB, N);
    bn_finalize_kernel<<<1, 128>>>(g1, be1, invN);

    // layer 2
    prep_kernel<1><<<qgrid, 256>>>((const float4*)bufB, bufH, N);
    prop_fp16_kernel<<<pgrid, 256>>>((const uint2*)bufH, bufA, N);
    gemm128_kernel<<<ggrid, 256, SMEM128>>>(bufA, W2, b2, bufB, N);
    bn_finalize_kernel<<<1, 128>>>(g2, be2, invN);

    // layer 3: GEMM first (prop and @W3 commute), then 40-wide prop
    //          with fused bias + log_softmax (fp32 for output precision)
    gemm40pre_kernel<<<ggrid, 256, SMEM40>>>(bufB, W3, bufA, N);
    prop40_kernel<<<pgrid, 256>>>(bufA, b3, out, N);
}